// round 1
// baseline (speedup 1.0000x reference)
#include <cuda_runtime.h>
#include <math.h>

#define D  64
#define L  50
#define NU 30000
#define NI 20000

// Scratch for projected features (allocation-free rule: device globals)
__device__ float g_uh[NU * D];
__device__ float g_ih[NI * D];

// ---------------------------------------------------------------------------
// feat [n, D] @ W [D, D] -> out [n, D].  One 64-thread block per row.
// ---------------------------------------------------------------------------
__global__ __launch_bounds__(64) void gemm64(const float* __restrict__ feat,
                                             const float* __restrict__ W,
                                             float* __restrict__ out) {
    const int row = blockIdx.x;
    const int tid = threadIdx.x;
    __shared__ float f[D];
    f[tid] = feat[row * D + tid];
    __syncthreads();
    float acc = 0.f;
#pragma unroll
    for (int d = 0; d < D; d++) acc += f[d] * W[d * D + tid];
    out[row * D + tid] = acc;
}

// ---------------------------------------------------------------------------
// DGSR attention reduce for one destination node per block (64 threads).
//   src_h : [Ns, D] projected source features (gathered via nbr)
//   dst_h : [N, D]  projected destination features
//   feat  : [N, D]  raw destination features (residual)
//   nbr   : [N, L]  neighbor ids into src_h
//   tim   : [N, L]  edge times
//   te    : [L, D]  time encoding (query side)
//   te_k  : [L, D]  time encoding (value side)
//   Wg    : [2D, D]
//   out   : [N, D]  elu(concat(h_long,h_short) @ Wg + feat)
// ---------------------------------------------------------------------------
__global__ __launch_bounds__(64) void attn(const float* __restrict__ src_h,
                                           const float* __restrict__ dst_h,
                                           const float* __restrict__ feat,
                                           const int*   __restrict__ nbr,
                                           const int*   __restrict__ tim,
                                           const float* __restrict__ te,
                                           const float* __restrict__ te_k,
                                           const float* __restrict__ Wg,
                                           float* __restrict__ out) {
    const int n   = blockIdx.x;
    const int tid = threadIdx.x;

    __shared__ float mb [L][D + 1];   // gathered mailbox
    __shared__ float tes[L][D + 1];   // te
    __shared__ float tks[L][D + 1];   // te_k
    __shared__ float h[D];
    __shared__ float ee[L];           // long-term logits -> alpha
    __shared__ float e1[L];           // short-term logits -> a1
    __shared__ int   ts[L];
    __shared__ int   nbs[L];
    __shared__ int   ro[L];
    __shared__ int   s_last;
    __shared__ float v[2 * D];

    // ---- Phase A: stage everything into shared ----
    h[tid] = dst_h[n * D + tid];
    if (tid < L) {
        ts[tid]  = tim[n * L + tid];
        nbs[tid] = nbr[n * L + tid];
    }
    __syncthreads();
#pragma unroll 2
    for (int l = 0; l < L; l++) {
        mb [l][tid] = src_h[nbs[l] * D + tid];
        tes[l][tid] = te  [l * D + tid];
        tks[l][tid] = te_k[l * D + tid];
    }

    // ---- Phase B: rank (stable argsort∘argsort) + argmax(first) ----
    if (tid < L) {
        const int t = ts[tid];
        int r = 0;
#pragma unroll 5
        for (int j = 0; j < L; j++) {
            const int tj = ts[j];
            r += (tj < t) || (tj == t && j < tid);
        }
        ro[tid] = L - 1 - r;
    }
    if (tid == 0) {
        int best = ts[0], bi = 0;
        for (int j = 1; j < L; j++)
            if (ts[j] > best) { best = ts[j]; bi = j; }
        s_last = bi;
    }
    __syncthreads();

    // ---- Phase C: attention logits (one edge per thread, tid<L) ----
    if (tid < L) {
        const int r    = ro[tid];
        const int last = s_last;
        float s = 0.f, s1 = 0.f;
#pragma unroll 8
        for (int d = 0; d < D; d++) {
            const float m = mb[tid][d];
            s  += (tes[r][d] + m) * h[d];
            s1 += mb[last][d] * m;
        }
        ee[tid] = s  * 0.125f;   // 1/sqrt(64)
        e1[tid] = s1 * 0.125f;
    }
    __syncthreads();

    // ---- Phase D: two softmaxes over L (warp 0) ----
    if (tid < 32) {
        float m = -1e30f, m1 = -1e30f;
        for (int l = tid; l < L; l += 32) {
            m  = fmaxf(m,  ee[l]);
            m1 = fmaxf(m1, e1[l]);
        }
#pragma unroll
        for (int o = 16; o > 0; o >>= 1) {
            m  = fmaxf(m,  __shfl_xor_sync(0xffffffffu, m,  o));
            m1 = fmaxf(m1, __shfl_xor_sync(0xffffffffu, m1, o));
        }
        float s = 0.f, s1 = 0.f;
        for (int l = tid; l < L; l += 32) {
            const float a  = __expf(ee[l] - m);
            const float a1 = __expf(e1[l] - m1);
            ee[l] = a;  e1[l] = a1;
            s += a;  s1 += a1;
        }
#pragma unroll
        for (int o = 16; o > 0; o >>= 1) {
            s  += __shfl_xor_sync(0xffffffffu, s,  o);
            s1 += __shfl_xor_sync(0xffffffffu, s1, o);
        }
        const float inv = 1.f / s, inv1 = 1.f / s1;
        for (int l = tid; l < L; l += 32) {
            ee[l] *= inv;
            e1[l] *= inv1;
        }
    }
    __syncthreads();

    // ---- Phase E: weighted sums (one feature dim per thread) ----
    float hl = 0.f, hs = 0.f;
#pragma unroll 5
    for (int l = 0; l < L; l++) {
        const float m = mb[l][tid];
        hl += ee[l] * (m + tks[ro[l]][tid]);
        hs += e1[l] * m;
    }
    v[tid]     = hl;
    v[D + tid] = hs;
    __syncthreads();

    // ---- Phase G: [1,2D] @ Wg[2D,D] + residual + ELU ----
    float acc = 0.f;
#pragma unroll 16
    for (int k = 0; k < 2 * D; k++) acc += v[k] * Wg[k * D + tid];
    acc += feat[n * D + tid];
    out[n * D + tid] = acc > 0.f ? acc : expm1f(acc);
}

// ---------------------------------------------------------------------------
extern "C" void kernel_launch(void* const* d_in, const int* in_sizes, int n_in,
                              void* d_out, int out_size) {
    const float* user_feat = (const float*)d_in[0];
    const float* item_feat = (const float*)d_in[1];
    const float* W_u       = (const float*)d_in[2];
    const float* W_i       = (const float*)d_in[3];
    const float* Wg_u      = (const float*)d_in[4];
    const float* Wg_i      = (const float*)d_in[5];
    const float* i_te      = (const float*)d_in[6];
    const float* i_te_k    = (const float*)d_in[7];
    const float* u_te      = (const float*)d_in[8];
    const float* u_te_k    = (const float*)d_in[9];
    const int*   item_nbr  = (const int*)d_in[10];
    const int*   item_time = (const int*)d_in[11];
    const int*   user_nbr  = (const int*)d_in[12];
    const int*   user_time = (const int*)d_in[13];

    float* user_out = (float*)d_out;            // [NU, D]
    float* item_out = (float*)d_out + NU * D;   // [NI, D]

    float* uh = nullptr;
    float* ih = nullptr;
    cudaGetSymbolAddress((void**)&uh, g_uh);
    cudaGetSymbolAddress((void**)&ih, g_ih);

    gemm64<<<NU, 64>>>(user_feat, W_u, uh);
    gemm64<<<NI, 64>>>(item_feat, W_i, ih);

    // items: mailbox of users ('by' edges)
    attn<<<NI, 64>>>(uh, ih, item_feat, item_nbr, item_time,
                     i_te, i_te_k, Wg_i, item_out);
    // users: mailbox of items ('pby' edges)
    attn<<<NU, 64>>>(ih, uh, user_feat, user_nbr, user_time,
                     u_te, u_te_k, Wg_u, user_out);
}

// round 2
// speedup vs baseline: 2.1675x; 2.1675x over previous
#include <cuda_runtime.h>
#include <math.h>

#define D  64
#define L  50
#define NU 30000
#define NI 20000

// Scratch for projected features (allocation-free rule: device globals)
__device__ float g_uh[NU * D];
__device__ float g_ih[NI * D];

// ---------------------------------------------------------------------------
// feat [n, D] @ W [D, D] -> out [n, D].  One 64-thread block per row.
// ---------------------------------------------------------------------------
__global__ __launch_bounds__(64) void gemm64(const float* __restrict__ feat,
                                             const float* __restrict__ W,
                                             float* __restrict__ out) {
    const int row = blockIdx.x;
    const int tid = threadIdx.x;
    __shared__ float f[D];
    f[tid] = feat[row * D + tid];
    __syncthreads();
    float acc = 0.f;
#pragma unroll
    for (int d = 0; d < D; d++) acc += f[d] * W[d * D + tid];
    out[row * D + tid] = acc;
}

// ---------------------------------------------------------------------------
// Fused DGSR attention for BOTH sides. blockIdx < NI -> item side, else user.
// One destination node per 64-thread block. te/te_k never staged in shared:
//   q[r]   = dot(te[r], h)                    (coalesced warp reductions)
//   h_long = sum_l a[l]*mb[l] + sum_r beta[r]*te_k[r],  beta[ro[l]] = a[l]
// (valid because ro is a permutation of 0..L-1)
// ---------------------------------------------------------------------------
__global__ __launch_bounds__(64) void attn_all(
    const float* __restrict__ uh,        const float* __restrict__ ih,
    const float* __restrict__ user_feat, const float* __restrict__ item_feat,
    const int*   __restrict__ item_nbr,  const int*   __restrict__ item_time,
    const int*   __restrict__ user_nbr,  const int*   __restrict__ user_time,
    const float* __restrict__ i_te,      const float* __restrict__ i_te_k,
    const float* __restrict__ u_te,      const float* __restrict__ u_te_k,
    const float* __restrict__ Wg_u,      const float* __restrict__ Wg_i,
    float* __restrict__ user_out,        float* __restrict__ item_out)
{
    const int b    = blockIdx.x;
    const int tid  = threadIdx.x;
    const int lane = tid & 31;
    const int wid  = tid >> 5;

    int n;
    const float *src_h, *dst_h, *feat, *te, *te_k, *Wg;
    const int *nbr, *tim;
    float *out;
    if (b < NI) {   // items: mailbox of users
        n = b;
        src_h = uh;  dst_h = ih;  feat = item_feat;
        nbr = item_nbr;  tim = item_time;
        te = i_te;  te_k = i_te_k;  Wg = Wg_i;  out = item_out;
    } else {        // users: mailbox of items
        n = b - NI;
        src_h = ih;  dst_h = uh;  feat = user_feat;
        nbr = user_nbr;  tim = user_time;
        te = u_te;  te_k = u_te_k;  Wg = Wg_u;  out = user_out;
    }

    __shared__ float mb[L][D + 1];    // gathered mailbox (conflict-free both ways)
    __shared__ float h[D];
    __shared__ float q[L];            // dot(te[r], h)
    __shared__ float ee[L], e1[L], beta[L];
    __shared__ float v[2 * D];
    __shared__ int   ts[L], nbs[L], ro[L];
    __shared__ int   s_last;

    // ---- stage h, times, neighbor ids ----
    h[tid] = dst_h[n * D + tid];
    if (tid < L) {
        ts[tid]  = tim[n * L + tid];
        nbs[tid] = nbr[n * L + tid];
    }
    __syncthreads();

    // ---- gather mailbox: float4, 4 rows per iteration (13 LDG.128/thread) ----
    {
        const int lane4 = tid & 15, row4 = tid >> 4;
#pragma unroll
        for (int l0 = 0; l0 < 48; l0 += 4) {
            const int l = l0 + row4;
            const float4 val = *((const float4*)(src_h + nbs[l] * D) + lane4);
            mb[l][lane4 * 4 + 0] = val.x;  mb[l][lane4 * 4 + 1] = val.y;
            mb[l][lane4 * 4 + 2] = val.z;  mb[l][lane4 * 4 + 3] = val.w;
        }
        if (row4 < 2) {
            const int l = 48 + row4;
            const float4 val = *((const float4*)(src_h + nbs[l] * D) + lane4);
            mb[l][lane4 * 4 + 0] = val.x;  mb[l][lane4 * 4 + 1] = val.y;
            mb[l][lane4 * 4 + 2] = val.z;  mb[l][lane4 * 4 + 3] = val.w;
        }
    }

    // ---- q[r] = dot(te[r], h): warp per r, coalesced L1-hot te reads ----
    for (int r = wid; r < L; r += 2) {
        float p = te[r * D + lane] * h[lane] + te[r * D + 32 + lane] * h[32 + lane];
#pragma unroll
        for (int o = 16; o > 0; o >>= 1) p += __shfl_xor_sync(0xffffffffu, p, o);
        if (lane == 0) q[r] = p;
    }

    // ---- ranks (stable argsort∘argsort semantics) ----
    if (tid < L) {
        const int t = ts[tid];
        int r = 0;
#pragma unroll 10
        for (int j = 0; j < L; j++) {
            const int tj = ts[j];
            r += (tj < t) || (tj == t && j < tid);
        }
        ro[tid] = L - 1 - r;
    }
    // ---- argmax (first index of max) in warp 0 ----
    if (wid == 0) {
        int bv = ts[lane], bi = lane;
        if (lane + 32 < L) {
            const int v2 = ts[lane + 32];
            if (v2 > bv) { bv = v2; bi = lane + 32; }
        }
#pragma unroll
        for (int o = 16; o > 0; o >>= 1) {
            const int ov = __shfl_xor_sync(0xffffffffu, bv, o);
            const int oi = __shfl_xor_sync(0xffffffffu, bi, o);
            if (ov > bv || (ov == bv && oi < bi)) { bv = ov; bi = oi; }
        }
        if (lane == 0) s_last = bi;
    }
    __syncthreads();

    // ---- attention logits: one edge per thread (tid < L) ----
    if (tid < L) {
        const int last = s_last;
        float s = 0.f, s1 = 0.f;
#pragma unroll 8
        for (int d = 0; d < D; d++) {
            const float m = mb[tid][d];
            s  += m * h[d];
            s1 += mb[last][d] * m;
        }
        ee[tid] = (s + q[ro[tid]]) * 0.125f;   // 1/sqrt(64)
        e1[tid] = s1 * 0.125f;
    }
    __syncthreads();

    // ---- two softmaxes over L (warp 0) ----
    if (wid == 0) {
        float m = -1e30f, m1 = -1e30f;
        for (int l = lane; l < L; l += 32) {
            m  = fmaxf(m,  ee[l]);
            m1 = fmaxf(m1, e1[l]);
        }
#pragma unroll
        for (int o = 16; o > 0; o >>= 1) {
            m  = fmaxf(m,  __shfl_xor_sync(0xffffffffu, m,  o));
            m1 = fmaxf(m1, __shfl_xor_sync(0xffffffffu, m1, o));
        }
        float s = 0.f, s1 = 0.f;
        for (int l = lane; l < L; l += 32) {
            const float a  = __expf(ee[l] - m);
            const float a1 = __expf(e1[l] - m1);
            ee[l] = a;  e1[l] = a1;
            s += a;  s1 += a1;
        }
#pragma unroll
        for (int o = 16; o > 0; o >>= 1) {
            s  += __shfl_xor_sync(0xffffffffu, s,  o);
            s1 += __shfl_xor_sync(0xffffffffu, s1, o);
        }
        const float inv = 1.f / s, inv1 = 1.f / s1;
        for (int l = lane; l < L; l += 32) {
            ee[l] *= inv;
            e1[l] *= inv1;
        }
    }
    __syncthreads();

    // ---- beta scatter + weighted mailbox sums (dim per thread) ----
    if (tid < L) beta[ro[tid]] = ee[tid];
    float hl = 0.f, hs = 0.f;
#pragma unroll 10
    for (int l = 0; l < L; l++) {
        const float m = mb[l][tid];
        hl += ee[l] * m;
        hs += e1[l] * m;
    }
    __syncthreads();
    // te_k term: coalesced L1-hot global reads
#pragma unroll 10
    for (int r = 0; r < L; r++) hl += beta[r] * te_k[r * D + tid];
    v[tid]     = hl;
    v[D + tid] = hs;
    __syncthreads();

    // ---- [1,2D] @ Wg[2D,D] + residual + ELU ----
    float acc = 0.f;
#pragma unroll 16
    for (int k = 0; k < 2 * D; k++) acc += v[k] * Wg[k * D + tid];
    acc += feat[n * D + tid];
    out[n * D + tid] = acc > 0.f ? acc : expm1f(acc);
}

// ---------------------------------------------------------------------------
extern "C" void kernel_launch(void* const* d_in, const int* in_sizes, int n_in,
                              void* d_out, int out_size) {
    const float* user_feat = (const float*)d_in[0];
    const float* item_feat = (const float*)d_in[1];
    const float* W_u       = (const float*)d_in[2];
    const float* W_i       = (const float*)d_in[3];
    const float* Wg_u      = (const float*)d_in[4];
    const float* Wg_i      = (const float*)d_in[5];
    const float* i_te      = (const float*)d_in[6];
    const float* i_te_k    = (const float*)d_in[7];
    const float* u_te      = (const float*)d_in[8];
    const float* u_te_k    = (const float*)d_in[9];
    const int*   item_nbr  = (const int*)d_in[10];
    const int*   item_time = (const int*)d_in[11];
    const int*   user_nbr  = (const int*)d_in[12];
    const int*   user_time = (const int*)d_in[13];

    float* user_out = (float*)d_out;            // [NU, D]
    float* item_out = (float*)d_out + NU * D;   // [NI, D]

    float* uh = nullptr;
    float* ih = nullptr;
    cudaGetSymbolAddress((void**)&uh, g_uh);
    cudaGetSymbolAddress((void**)&ih, g_ih);

    gemm64<<<NU, 64>>>(user_feat, W_u, uh);
    gemm64<<<NI, 64>>>(item_feat, W_i, ih);

    attn_all<<<NI + NU, 64>>>(uh, ih, user_feat, item_feat,
                              item_nbr, item_time, user_nbr, user_time,
                              i_te, i_te_k, u_te, u_te_k,
                              Wg_u, Wg_i, user_out, item_out);
}

// round 3
// speedup vs baseline: 2.5679x; 1.1847x over previous
#include <cuda_runtime.h>
#include <cuda_fp16.h>
#include <math.h>

#define D  64
#define L  50
#define NU 30000
#define NI 20000

// Projected features in fp16 (halves gather bytes + smem mailbox footprint)
__device__ __half g_uh[NU * D];
__device__ __half g_ih[NI * D];

// ---------------------------------------------------------------------------
// Both feature projections in one launch: row b<NU -> user, else item.
// out = half(feat @ W)
// ---------------------------------------------------------------------------
__global__ __launch_bounds__(64) void gemm_both(
    const float* __restrict__ user_feat, const float* __restrict__ item_feat,
    const float* __restrict__ W_u,       const float* __restrict__ W_i)
{
    const int b   = blockIdx.x;
    const int tid = threadIdx.x;
    const float* feat; const float* W; __half* out; int row;
    if (b < NU) { feat = user_feat; W = W_u; out = g_uh; row = b; }
    else        { feat = item_feat; W = W_i; out = g_ih; row = b - NU; }

    __shared__ float f[D];
    f[tid] = feat[row * D + tid];
    __syncthreads();
    float acc = 0.f;
#pragma unroll
    for (int d = 0; d < D; d++) acc += f[d] * W[d * D + tid];
    out[row * D + tid] = __float2half(acc);
}

// ---------------------------------------------------------------------------
// Fused DGSR attention, both sides (blockIdx < NI -> item side, else user).
// One destination node per 64-thread block; mailbox staged in fp16 shared.
//   q[r]   = dot(te[r], h)
//   h_long = sum_l a[l]*mb[l] + sum_r beta[r]*te_k[r],  beta[ro[l]] = a[l]
// ---------------------------------------------------------------------------
#define MBP 66   // row stride in halves: 132B -> conflict-free rows & cols

__global__ __launch_bounds__(64) void attn_all(
    const float* __restrict__ user_feat, const float* __restrict__ item_feat,
    const int*   __restrict__ item_nbr,  const int*   __restrict__ item_time,
    const int*   __restrict__ user_nbr,  const int*   __restrict__ user_time,
    const float* __restrict__ i_te,      const float* __restrict__ i_te_k,
    const float* __restrict__ u_te,      const float* __restrict__ u_te_k,
    const float* __restrict__ Wg_u,      const float* __restrict__ Wg_i,
    float* __restrict__ user_out,        float* __restrict__ item_out)
{
    const int b    = blockIdx.x;
    const int tid  = threadIdx.x;
    const int lane = tid & 31;
    const int wid  = tid >> 5;

    int n;
    const __half *src_h, *dst_h;
    const float *feat, *te, *te_k, *Wg;
    const int *nbr, *tim;
    float *out;
    if (b < NI) {   // items: mailbox of users
        n = b;
        src_h = g_uh;  dst_h = g_ih;  feat = item_feat;
        nbr = item_nbr;  tim = item_time;
        te = i_te;  te_k = i_te_k;  Wg = Wg_i;  out = item_out;
    } else {        // users: mailbox of items
        n = b - NI;
        src_h = g_ih;  dst_h = g_uh;  feat = user_feat;
        nbr = user_nbr;  tim = user_time;
        te = u_te;  te_k = u_te_k;  Wg = Wg_u;  out = user_out;
    }

    __shared__ __half mb[L][MBP];     // gathered mailbox (fp16)
    __shared__ float h[D];
    __shared__ float q[L];
    __shared__ float ee[L], e1[L], beta[L];
    __shared__ float v[2 * D];
    __shared__ int   ts[L], nbs[L], ro[L];
    __shared__ int   s_last;

    // ---- stage h, times, neighbor ids ----
    h[tid] = __half2float(dst_h[n * D + tid]);
    if (tid < L) {
        ts[tid]  = tim[n * L + tid];
        nbs[tid] = nbr[n * L + tid];
    }
    __syncthreads();

    // ---- gather mailbox: 8B loads, 4 rows per pass (row = 16 lanes x 8B) ----
    {
        const int lane4 = tid & 15, row4 = tid >> 4;
#pragma unroll
        for (int l0 = 0; l0 < 48; l0 += 4) {
            const int l = l0 + row4;
            const uint2 val = *((const uint2*)(src_h + nbs[l] * D) + lane4);
            *(unsigned*)&mb[l][lane4 * 4 + 0] = val.x;
            *(unsigned*)&mb[l][lane4 * 4 + 2] = val.y;
        }
        if (row4 < 2) {
            const int l = 48 + row4;
            const uint2 val = *((const uint2*)(src_h + nbs[l] * D) + lane4);
            *(unsigned*)&mb[l][lane4 * 4 + 0] = val.x;
            *(unsigned*)&mb[l][lane4 * 4 + 2] = val.y;
        }
    }

    // ---- q[r] = dot(te[r], h): warp per r, coalesced L1-hot te reads ----
    for (int r = wid; r < L; r += 2) {
        float p = te[r * D + lane] * h[lane] + te[r * D + 32 + lane] * h[32 + lane];
#pragma unroll
        for (int o = 16; o > 0; o >>= 1) p += __shfl_xor_sync(0xffffffffu, p, o);
        if (lane == 0) q[r] = p;
    }

    // ---- ranks (stable argsort∘argsort semantics) ----
    if (tid < L) {
        const int t = ts[tid];
        int r = 0;
#pragma unroll 10
        for (int j = 0; j < L; j++) {
            const int tj = ts[j];
            r += (tj < t) || (tj == t && j < tid);
        }
        ro[tid] = L - 1 - r;
    }
    // ---- argmax (first index of max) in warp 0 ----
    if (wid == 0) {
        int bv = ts[lane], bi = lane;
        if (lane + 32 < L) {
            const int v2 = ts[lane + 32];
            if (v2 > bv) { bv = v2; bi = lane + 32; }
        }
#pragma unroll
        for (int o = 16; o > 0; o >>= 1) {
            const int ov = __shfl_xor_sync(0xffffffffu, bv, o);
            const int oi = __shfl_xor_sync(0xffffffffu, bi, o);
            if (ov > bv || (ov == bv && oi < bi)) { bv = ov; bi = oi; }
        }
        if (lane == 0) s_last = bi;
    }
    __syncthreads();

    // ---- attention logits: one edge per thread (tid < L), half2 loads ----
    if (tid < L) {
        const __half2* rowp  = (const __half2*)&mb[tid][0];
        const __half2* lastp = (const __half2*)&mb[s_last][0];
        float s = 0.f, s1 = 0.f;
#pragma unroll
        for (int i = 0; i < D / 2; i++) {
            const float2 m  = __half22float2(rowp[i]);
            const float2 ml = __half22float2(lastp[i]);
            s  += m.x * h[2 * i] + m.y * h[2 * i + 1];
            s1 += ml.x * m.x + ml.y * m.y;
        }
        ee[tid] = (s + q[ro[tid]]) * 0.125f;   // 1/sqrt(64)
        e1[tid] = s1 * 0.125f;
    }
    __syncthreads();

    // ---- two softmaxes over L (warp 0) ----
    if (wid == 0) {
        float m = -1e30f, m1 = -1e30f;
        for (int l = lane; l < L; l += 32) {
            m  = fmaxf(m,  ee[l]);
            m1 = fmaxf(m1, e1[l]);
        }
#pragma unroll
        for (int o = 16; o > 0; o >>= 1) {
            m  = fmaxf(m,  __shfl_xor_sync(0xffffffffu, m,  o));
            m1 = fmaxf(m1, __shfl_xor_sync(0xffffffffu, m1, o));
        }
        float s = 0.f, s1 = 0.f;
        for (int l = lane; l < L; l += 32) {
            const float a  = __expf(ee[l] - m);
            const float a1 = __expf(e1[l] - m1);
            ee[l] = a;  e1[l] = a1;
            s += a;  s1 += a1;
        }
#pragma unroll
        for (int o = 16; o > 0; o >>= 1) {
            s  += __shfl_xor_sync(0xffffffffu, s,  o);
            s1 += __shfl_xor_sync(0xffffffffu, s1, o);
        }
        const float inv = 1.f / s, inv1 = 1.f / s1;
        for (int l = lane; l < L; l += 32) {
            ee[l] *= inv;
            e1[l] *= inv1;
        }
    }
    __syncthreads();

    // ---- beta scatter + weighted mailbox sums (dim per thread) ----
    if (tid < L) beta[ro[tid]] = ee[tid];
    float hl = 0.f, hs = 0.f;
#pragma unroll 10
    for (int l = 0; l < L; l++) {
        const float m = __half2float(mb[l][tid]);
        hl += ee[l] * m;
        hs += e1[l] * m;
    }
    __syncthreads();
    // te_k term: coalesced L1-hot global reads (ro is a permutation)
#pragma unroll 10
    for (int r = 0; r < L; r++) hl += beta[r] * te_k[r * D + tid];
    v[tid]     = hl;
    v[D + tid] = hs;
    __syncthreads();

    // ---- [1,2D] @ Wg[2D,D] + residual + ELU ----
    float acc = 0.f;
#pragma unroll 16
    for (int k = 0; k < 2 * D; k++) acc += v[k] * Wg[k * D + tid];
    acc += feat[n * D + tid];
    out[n * D + tid] = acc > 0.f ? acc : expm1f(acc);
}

// ---------------------------------------------------------------------------
extern "C" void kernel_launch(void* const* d_in, const int* in_sizes, int n_in,
                              void* d_out, int out_size) {
    const float* user_feat = (const float*)d_in[0];
    const float* item_feat = (const float*)d_in[1];
    const float* W_u       = (const float*)d_in[2];
    const float* W_i       = (const float*)d_in[3];
    const float* Wg_u      = (const float*)d_in[4];
    const float* Wg_i      = (const float*)d_in[5];
    const float* i_te      = (const float*)d_in[6];
    const float* i_te_k    = (const float*)d_in[7];
    const float* u_te      = (const float*)d_in[8];
    const float* u_te_k    = (const float*)d_in[9];
    const int*   item_nbr  = (const int*)d_in[10];
    const int*   item_time = (const int*)d_in[11];
    const int*   user_nbr  = (const int*)d_in[12];
    const int*   user_time = (const int*)d_in[13];

    float* user_out = (float*)d_out;            // [NU, D]
    float* item_out = (float*)d_out + NU * D;   // [NI, D]

    gemm_both<<<NU + NI, 64>>>(user_feat, item_feat, W_u, W_i);

    attn_all<<<NI + NU, 64>>>(user_feat, item_feat,
                              item_nbr, item_time, user_nbr, user_time,
                              i_te, i_te_k, u_te, u_te_k,
                              Wg_u, Wg_i, user_out, item_out);
}

// round 4
// speedup vs baseline: 3.0285x; 1.1794x over previous
#include <cuda_runtime.h>
#include <cuda_fp16.h>
#include <math.h>

#define D  64
#define L  50
#define NU 30000
#define NI 20000

#define QN   64                 // nodes per q_gemm block
#define NBI  ((NI + QN - 1) / QN)   // 313
#define NBU  ((NU + QN - 1) / QN)   // 469

// Projected features in fp16 (halves gather bytes + smem mailbox footprint)
__device__ __half g_uh[NU * D];
__device__ __half g_ih[NI * D];
// Precomputed time-encoding logit offsets q[n][r] = dot(te[r], h_n)
__device__ float  g_q[(NI + NU) * L];

// ---------------------------------------------------------------------------
// Both feature projections in one launch: row b<NU -> user, else item.
// ---------------------------------------------------------------------------
__global__ __launch_bounds__(64) void gemm_both(
    const float* __restrict__ user_feat, const float* __restrict__ item_feat,
    const float* __restrict__ W_u,       const float* __restrict__ W_i)
{
    const int b   = blockIdx.x;
    const int tid = threadIdx.x;
    const float* feat; const float* W; __half* out; int row;
    if (b < NU) { feat = user_feat; W = W_u; out = g_uh; row = b; }
    else        { feat = item_feat; W = W_i; out = g_ih; row = b - NU; }

    __shared__ float f[D];
    f[tid] = feat[row * D + tid];
    __syncthreads();
    float acc = 0.f;
#pragma unroll
    for (int d = 0; d < D; d++) acc += f[d] * W[d * D + tid];
    out[row * D + tid] = __float2half(acc);
}

// ---------------------------------------------------------------------------
// Q[n][r] = dot(te[r], h_n) as a tiled GEMM: 64 nodes x 50 r per block.
// Operands staged TRANSPOSED in shared (hT[d][n], tT[d][r]); 4x4 register
// tiles -> ~20 warp-level L1 ops per node instead of ~500 inside attn.
// ---------------------------------------------------------------------------
#define HTP 68   // hT row stride (halves): 136B, 8B-aligned, conflict-free use
#define TTP 56   // tT row stride (halves): 112B, 8B-aligned

__global__ __launch_bounds__(256) void q_gemm(
    const float* __restrict__ i_te, const float* __restrict__ u_te)
{
    const bool item = blockIdx.x < NBI;
    const int  n0   = item ? blockIdx.x * QN : (blockIdx.x - NBI) * QN;
    const int  N    = item ? NI : NU;
    const __half* H = item ? g_ih : g_uh;
    const float* te = item ? i_te : u_te;
    float* qout     = g_q + (item ? 0 : NI * L);

    __shared__ __half hT[D][HTP];   // hT[d][n_local]
    __shared__ __half tT[D][TTP];   // tT[d][r], r zero-padded to 52

    const int t = threadIdx.x, lane = t & 31, w = t >> 5;

    // stage hT (transposed): warp w handles local nodes w, w+8, ...
    for (int j = w; j < QN; j += 8) {
        const int n = n0 + j;
        __half a = __half(0.f), b = __half(0.f);
        if (n < N) { a = H[n * D + lane]; b = H[n * D + 32 + lane]; }
        hT[lane][j]      = a;
        hT[32 + lane][j] = b;
    }
    // stage tT (transposed, fp32->fp16): warp w handles r = w, w+8, ...
    for (int r = w; r < 52; r += 8) {
        float a = 0.f, b = 0.f;
        if (r < L) { a = te[r * D + lane]; b = te[r * D + 32 + lane]; }
        tT[lane][r]      = __float2half(a);
        tT[32 + lane][r] = __float2half(b);
    }
    __syncthreads();

    // compute: 16 node-groups x 13 r-groups, 4x4 register tile each
    if (t < 208) {
        const int nb = (t & 15) * 4;        // local node base
        const int rb = (t >> 4) * 4;        // r base (<= 48)
        float acc[4][4];
#pragma unroll
        for (int i = 0; i < 4; i++)
#pragma unroll
            for (int j = 0; j < 4; j++) acc[i][j] = 0.f;

#pragma unroll
        for (int d = 0; d < D; d++) {
            const __half2 ha = *(const __half2*)&hT[d][nb];
            const __half2 hb = *(const __half2*)&hT[d][nb + 2];
            const __half2 ta = *(const __half2*)&tT[d][rb];
            const __half2 tb = *(const __half2*)&tT[d][rb + 2];
            const float h0 = __low2float(ha), h1 = __high2float(ha);
            const float h2 = __low2float(hb), h3 = __high2float(hb);
            const float t0 = __low2float(ta), t1 = __high2float(ta);
            const float t2 = __low2float(tb), t3 = __high2float(tb);
            acc[0][0] += h0 * t0; acc[0][1] += h0 * t1; acc[0][2] += h0 * t2; acc[0][3] += h0 * t3;
            acc[1][0] += h1 * t0; acc[1][1] += h1 * t1; acc[1][2] += h1 * t2; acc[1][3] += h1 * t3;
            acc[2][0] += h2 * t0; acc[2][1] += h2 * t1; acc[2][2] += h2 * t2; acc[2][3] += h2 * t3;
            acc[3][0] += h3 * t0; acc[3][1] += h3 * t1; acc[3][2] += h3 * t2; acc[3][3] += h3 * t3;
        }
#pragma unroll
        for (int i = 0; i < 4; i++) {
            const int n = n0 + nb + i;
            if (n < N) {
#pragma unroll
                for (int j = 0; j < 4; j++)
                    if (rb + j < L) qout[n * L + rb + j] = acc[i][j];
            }
        }
    }
}

// ---------------------------------------------------------------------------
// Fused DGSR attention, both sides (blockIdx < NI -> item side, else user).
// q-loop removed: logit offsets read from precomputed g_q.
// ---------------------------------------------------------------------------
#define MBP 66   // mailbox row stride in halves: conflict-free rows & cols

__global__ __launch_bounds__(64) void attn_all(
    const float* __restrict__ user_feat, const float* __restrict__ item_feat,
    const int*   __restrict__ item_nbr,  const int*   __restrict__ item_time,
    const int*   __restrict__ user_nbr,  const int*   __restrict__ user_time,
    const float* __restrict__ i_te_k,    const float* __restrict__ u_te_k,
    const float* __restrict__ Wg_u,      const float* __restrict__ Wg_i,
    float* __restrict__ user_out,        float* __restrict__ item_out)
{
    const int b    = blockIdx.x;
    const int tid  = threadIdx.x;
    const int lane = tid & 31;
    const int wid  = tid >> 5;

    int n;
    const __half *src_h, *dst_h;
    const float *feat, *te_k, *Wg, *qrow;
    const int *nbr, *tim;
    float *out;
    if (b < NI) {   // items: mailbox of users
        n = b;
        src_h = g_uh;  dst_h = g_ih;  feat = item_feat;
        nbr = item_nbr;  tim = item_time;
        te_k = i_te_k;  Wg = Wg_i;  out = item_out;
        qrow = g_q + n * L;
    } else {        // users: mailbox of items
        n = b - NI;
        src_h = g_ih;  dst_h = g_uh;  feat = user_feat;
        nbr = user_nbr;  tim = user_time;
        te_k = u_te_k;  Wg = Wg_u;  out = user_out;
        qrow = g_q + NI * L + n * L;
    }

    __shared__ __half mb[L][MBP];     // gathered mailbox (fp16)
    __shared__ float h[D];
    __shared__ float ee[L], e1[L], beta[L];
    __shared__ float v[2 * D];
    __shared__ int   ts[L], nbs[L], ro[L];
    __shared__ int   s_last;

    // ---- stage h, times, neighbor ids ----
    h[tid] = __half2float(dst_h[n * D + tid]);
    if (tid < L) {
        ts[tid]  = tim[n * L + tid];
        nbs[tid] = nbr[n * L + tid];
    }
    __syncthreads();

    // ---- gather mailbox: 8B loads, 4 rows per pass (row = 16 lanes x 8B) ----
    {
        const int lane4 = tid & 15, row4 = tid >> 4;
#pragma unroll
        for (int l0 = 0; l0 < 48; l0 += 4) {
            const int l = l0 + row4;
            const uint2 val = *((const uint2*)(src_h + nbs[l] * D) + lane4);
            *(unsigned*)&mb[l][lane4 * 4 + 0] = val.x;
            *(unsigned*)&mb[l][lane4 * 4 + 2] = val.y;
        }
        if (row4 < 2) {
            const int l = 48 + row4;
            const uint2 val = *((const uint2*)(src_h + nbs[l] * D) + lane4);
            *(unsigned*)&mb[l][lane4 * 4 + 0] = val.x;
            *(unsigned*)&mb[l][lane4 * 4 + 2] = val.y;
        }
    }

    // ---- ranks (stable argsort∘argsort semantics) ----
    if (tid < L) {
        const int t = ts[tid];
        int r = 0;
#pragma unroll 10
        for (int j = 0; j < L; j++) {
            const int tj = ts[j];
            r += (tj < t) || (tj == t && j < tid);
        }
        ro[tid] = L - 1 - r;
    }
    // ---- argmax (first index of max) in warp 0 ----
    if (wid == 0) {
        int bv = ts[lane], bi = lane;
        if (lane + 32 < L) {
            const int v2 = ts[lane + 32];
            if (v2 > bv) { bv = v2; bi = lane + 32; }
        }
#pragma unroll
        for (int o = 16; o > 0; o >>= 1) {
            const int ov = __shfl_xor_sync(0xffffffffu, bv, o);
            const int oi = __shfl_xor_sync(0xffffffffu, bi, o);
            if (ov > bv || (ov == bv && oi < bi)) { bv = ov; bi = oi; }
        }
        if (lane == 0) s_last = bi;
    }
    __syncthreads();

    // ---- attention logits: one edge per thread (tid < L), half2 loads ----
    if (tid < L) {
        const __half2* rowp  = (const __half2*)&mb[tid][0];
        const __half2* lastp = (const __half2*)&mb[s_last][0];
        float s = 0.f, s1 = 0.f;
#pragma unroll
        for (int i = 0; i < D / 2; i++) {
            const float2 m  = __half22float2(rowp[i]);
            const float2 ml = __half22float2(lastp[i]);
            s  += m.x * h[2 * i] + m.y * h[2 * i + 1];
            s1 += ml.x * m.x + ml.y * m.y;
        }
        ee[tid] = (s + qrow[ro[tid]]) * 0.125f;   // 1/sqrt(64)
        e1[tid] = s1 * 0.125f;
    }
    __syncthreads();

    // ---- two softmaxes over L (warp 0) ----
    if (wid == 0) {
        float m = -1e30f, m1 = -1e30f;
        for (int l = lane; l < L; l += 32) {
            m  = fmaxf(m,  ee[l]);
            m1 = fmaxf(m1, e1[l]);
        }
#pragma unroll
        for (int o = 16; o > 0; o >>= 1) {
            m  = fmaxf(m,  __shfl_xor_sync(0xffffffffu, m,  o));
            m1 = fmaxf(m1, __shfl_xor_sync(0xffffffffu, m1, o));
        }
        float s = 0.f, s1 = 0.f;
        for (int l = lane; l < L; l += 32) {
            const float a  = __expf(ee[l] - m);
            const float a1 = __expf(e1[l] - m1);
            ee[l] = a;  e1[l] = a1;
            s += a;  s1 += a1;
        }
#pragma unroll
        for (int o = 16; o > 0; o >>= 1) {
            s  += __shfl_xor_sync(0xffffffffu, s,  o);
            s1 += __shfl_xor_sync(0xffffffffu, s1, o);
        }
        const float inv = 1.f / s, inv1 = 1.f / s1;
        for (int l = lane; l < L; l += 32) {
            ee[l] *= inv;
            e1[l] *= inv1;
        }
    }
    __syncthreads();

    // ---- beta scatter + weighted mailbox sums (dim per thread) ----
    if (tid < L) beta[ro[tid]] = ee[tid];
    float hl = 0.f, hs = 0.f;
#pragma unroll 10
    for (int l = 0; l < L; l++) {
        const float m = __half2float(mb[l][tid]);
        hl += ee[l] * m;
        hs += e1[l] * m;
    }
    __syncthreads();
    // te_k term: coalesced L1-hot global reads (ro is a permutation)
#pragma unroll 10
    for (int r = 0; r < L; r++) hl += beta[r] * te_k[r * D + tid];
    v[tid]     = hl;
    v[D + tid] = hs;
    __syncthreads();

    // ---- [1,2D] @ Wg[2D,D] + residual + ELU ----
    float acc = 0.f;
#pragma unroll 16
    for (int k = 0; k < 2 * D; k++) acc += v[k] * Wg[k * D + tid];
    acc += feat[n * D + tid];
    out[n * D + tid] = acc > 0.f ? acc : expm1f(acc);
}

// ---------------------------------------------------------------------------
extern "C" void kernel_launch(void* const* d_in, const int* in_sizes, int n_in,
                              void* d_out, int out_size) {
    const float* user_feat = (const float*)d_in[0];
    const float* item_feat = (const float*)d_in[1];
    const float* W_u       = (const float*)d_in[2];
    const float* W_i       = (const float*)d_in[3];
    const float* Wg_u      = (const float*)d_in[4];
    const float* Wg_i      = (const float*)d_in[5];
    const float* i_te      = (const float*)d_in[6];
    const float* i_te_k    = (const float*)d_in[7];
    const float* u_te      = (const float*)d_in[8];
    const float* u_te_k    = (const float*)d_in[9];
    const int*   item_nbr  = (const int*)d_in[10];
    const int*   item_time = (const int*)d_in[11];
    const int*   user_nbr  = (const int*)d_in[12];
    const int*   user_time = (const int*)d_in[13];

    float* user_out = (float*)d_out;            // [NU, D]
    float* item_out = (float*)d_out + NU * D;   // [NI, D]

    gemm_both<<<NU + NI, 64>>>(user_feat, item_feat, W_u, W_i);
    q_gemm<<<NBI + NBU, 256>>>(i_te, u_te);

    attn_all<<<NI + NU, 64>>>(user_feat, item_feat,
                              item_nbr, item_time, user_nbr, user_time,
                              i_te_k, u_te_k,
                              Wg_u, Wg_i, user_out, item_out);
}

// round 5
// speedup vs baseline: 3.2777x; 1.0823x over previous
#include <cuda_runtime.h>
#include <cuda_fp16.h>
#include <math.h>

#define D  64
#define L  50
#define NU 30000
#define NI 20000
#define NT (NU + NI)        // 50000 total nodes
#define KM 178              // m-vector length: 64 hl | 64 hs | 50 beta

#define QN   64
#define NBI  ((NI + QN - 1) / QN)   // 313
#define NBU  ((NU + QN - 1) / QN)   // 469

#define PBI  ((NI + 63) / 64)       // 313 proj blocks (item)
#define PBU  ((NU + 63) / 64)       // 469 proj blocks (user)

// device scratch (allocation-free rule)
__device__ __half g_uh[NU * D];
__device__ __half g_ih[NI * D];
__device__ float  g_q[NT * L];          // q[n][r] = dot(te[r], h_n)
__device__ float  g_m[NT * KM];         // per-node m vector
__device__ float  g_wcat[2][KM * D];    // [0]=item side, [1]=user side

// ---------------------------------------------------------------------------
// proj: feat[N,64] @ W[64,64] -> half. 64 rows x 64 cols per 256-thread block,
// 4x4 register tiles, both operands staged in shared.
// blocks [0, PBU): user side; [PBU, PBU+PBI): item side.
// ---------------------------------------------------------------------------
__global__ __launch_bounds__(256) void proj(
    const float* __restrict__ user_feat, const float* __restrict__ item_feat,
    const float* __restrict__ W_u,       const float* __restrict__ W_i)
{
    const bool user = blockIdx.x < PBU;
    const int  r0   = (user ? blockIdx.x : blockIdx.x - PBU) * 64;
    const int  N    = user ? NU : NI;
    const float* feat = user ? user_feat : item_feat;
    const float* W    = user ? W_u : W_i;
    __half* outp      = user ? g_uh : g_ih;

    __shared__ float fT[D * 68];   // fT[k][row], pad 68
    __shared__ float Ws[D * 68];   // Ws[k][c],  pad 68

    const int t = threadIdx.x, lane = t & 31, w = t >> 5;

    // stage fT transposed: warp w -> rows w*8..w*8+7
#pragma unroll
    for (int i = 0; i < 8; i++) {
        const int r = w * 8 + i, row = r0 + r;
        float a = 0.f, b = 0.f;
        if (row < N) { a = feat[row * D + lane]; b = feat[row * D + 32 + lane]; }
        fT[lane * 68 + r]        = a;
        fT[(32 + lane) * 68 + r] = b;
    }
    // stage W (already [k][c])
#pragma unroll
    for (int idx = t; idx < D * D; idx += 256)
        Ws[(idx >> 6) * 68 + (idx & 63)] = W[idx];
    __syncthreads();

    const int rg = t >> 4, cg = t & 15;
    float acc[4][4];
#pragma unroll
    for (int i = 0; i < 4; i++)
#pragma unroll
        for (int j = 0; j < 4; j++) acc[i][j] = 0.f;

#pragma unroll 8
    for (int k = 0; k < D; k++) {
        const float4 fv = *(const float4*)&fT[k * 68 + rg * 4];
        const float4 wv = *(const float4*)&Ws[k * 68 + cg * 4];
        const float f[4] = {fv.x, fv.y, fv.z, fv.w};
        const float wc[4] = {wv.x, wv.y, wv.z, wv.w};
#pragma unroll
        for (int i = 0; i < 4; i++)
#pragma unroll
            for (int j = 0; j < 4; j++) acc[i][j] += f[i] * wc[j];
    }
#pragma unroll
    for (int i = 0; i < 4; i++) {
        const int row = r0 + rg * 4 + i;
        if (row < N) {
            __half2 p0 = __floats2half2_rn(acc[i][0], acc[i][1]);
            __half2 p1 = __floats2half2_rn(acc[i][2], acc[i][3]);
            *(__half2*)&outp[row * D + cg * 4]     = p0;
            *(__half2*)&outp[row * D + cg * 4 + 2] = p1;
        }
    }
}

// ---------------------------------------------------------------------------
// q_gemm: Q[n][r] = dot(te[r], h_n). 64 nodes x 50 r per 256-thread block.
// ---------------------------------------------------------------------------
#define HTP 68
#define TTP 56

__global__ __launch_bounds__(256) void q_gemm(
    const float* __restrict__ i_te, const float* __restrict__ u_te)
{
    const bool item = blockIdx.x < NBI;
    const int  n0   = item ? blockIdx.x * QN : (blockIdx.x - NBI) * QN;
    const int  N    = item ? NI : NU;
    const __half* H = item ? g_ih : g_uh;
    const float* te = item ? i_te : u_te;
    float* qout     = g_q + (item ? 0 : NI * L);

    __shared__ __half hT[D][HTP];
    __shared__ __half tT[D][TTP];

    const int t = threadIdx.x, lane = t & 31, w = t >> 5;

    for (int j = w; j < QN; j += 8) {
        const int n = n0 + j;
        __half a = __half(0.f), b = __half(0.f);
        if (n < N) { a = H[n * D + lane]; b = H[n * D + 32 + lane]; }
        hT[lane][j]      = a;
        hT[32 + lane][j] = b;
    }
    for (int r = w; r < 52; r += 8) {
        float a = 0.f, b = 0.f;
        if (r < L) { a = te[r * D + lane]; b = te[r * D + 32 + lane]; }
        tT[lane][r]      = __float2half(a);
        tT[32 + lane][r] = __float2half(b);
    }
    __syncthreads();

    if (t < 208) {
        const int nb = (t & 15) * 4;
        const int rb = (t >> 4) * 4;
        float acc[4][4];
#pragma unroll
        for (int i = 0; i < 4; i++)
#pragma unroll
            for (int j = 0; j < 4; j++) acc[i][j] = 0.f;

#pragma unroll
        for (int d = 0; d < D; d++) {
            const __half2 ha = *(const __half2*)&hT[d][nb];
            const __half2 hb = *(const __half2*)&hT[d][nb + 2];
            const __half2 ta = *(const __half2*)&tT[d][rb];
            const __half2 tb = *(const __half2*)&tT[d][rb + 2];
            const float h0 = __low2float(ha), h1 = __high2float(ha);
            const float h2 = __low2float(hb), h3 = __high2float(hb);
            const float t0 = __low2float(ta), t1 = __high2float(ta);
            const float t2 = __low2float(tb), t3 = __high2float(tb);
            acc[0][0] += h0 * t0; acc[0][1] += h0 * t1; acc[0][2] += h0 * t2; acc[0][3] += h0 * t3;
            acc[1][0] += h1 * t0; acc[1][1] += h1 * t1; acc[1][2] += h1 * t2; acc[1][3] += h1 * t3;
            acc[2][0] += h2 * t0; acc[2][1] += h2 * t1; acc[2][2] += h2 * t2; acc[2][3] += h2 * t3;
            acc[3][0] += h3 * t0; acc[3][1] += h3 * t1; acc[3][2] += h3 * t2; acc[3][3] += h3 * t3;
        }
#pragma unroll
        for (int i = 0; i < 4; i++) {
            const int n = n0 + nb + i;
            if (n < N) {
#pragma unroll
                for (int j = 0; j < 4; j++)
                    if (rb + j < L) qout[n * L + rb + j] = acc[i][j];
            }
        }
    }
}

// ---------------------------------------------------------------------------
// prep_wcat: Wcat = [Wg(128x64) ; te_k(50x64) @ Wg[0:64](64x64)]
// block 0 = item side, block 1 = user side
// ---------------------------------------------------------------------------
__global__ __launch_bounds__(256) void prep_wcat(
    const float* __restrict__ Wg_i, const float* __restrict__ i_te_k,
    const float* __restrict__ Wg_u, const float* __restrict__ u_te_k)
{
    const int s = blockIdx.x;                 // 0 item, 1 user
    const float* Wg   = s == 0 ? Wg_i : Wg_u;
    const float* te_k = s == 0 ? i_te_k : u_te_k;
    float* out = g_wcat[s];

    const int t = threadIdx.x;
    __shared__ float Wsh[D * D];              // Wg top half [d][c]

    for (int idx = t; idx < D * D; idx += 256) Wsh[idx] = Wg[idx];
    for (int idx = t; idx < 2 * D * D; idx += 256) out[idx] = Wg[idx];
    __syncthreads();

    for (int idx = t; idx < L * D; idx += 256) {
        const int r = idx >> 6, c = idx & 63;
        float acc = 0.f;
#pragma unroll 8
        for (int d = 0; d < D; d++) acc += te_k[r * D + d] * Wsh[d * D + c];
        out[(2 * D + r) * D + c] = acc;
    }
}

// ---------------------------------------------------------------------------
// attn_all: gather + ranks + logits + softmax + weighted sums only.
// Emits m[n] = [hl_mb | hs | beta] to g_m. No dense algebra.
// ---------------------------------------------------------------------------
#define MBP 66

__global__ __launch_bounds__(64) void attn_all(
    const int* __restrict__ item_nbr, const int* __restrict__ item_time,
    const int* __restrict__ user_nbr, const int* __restrict__ user_time)
{
    const int b    = blockIdx.x;
    const int tid  = threadIdx.x;
    const int lane = tid & 31;
    const int wid  = tid >> 5;

    int n;
    const __half *src_h, *dst_h;
    const int *nbr, *tim;
    if (b < NI) {
        n = b;
        src_h = g_uh;  dst_h = g_ih;
        nbr = item_nbr;  tim = item_time;
    } else {
        n = b - NI;
        src_h = g_ih;  dst_h = g_uh;
        nbr = user_nbr;  tim = user_time;
    }
    const float* qrow = g_q + b * L;          // same ordering as blocks
    float* mrow = g_m + b * KM;

    __shared__ __half mb[L][MBP];
    __shared__ float h[D];
    __shared__ float ee[L], e1[L];
    __shared__ int   ts[L], nbs[L], ro[L];
    __shared__ int   s_last;

    h[tid] = __half2float(dst_h[n * D + tid]);
    if (tid < L) {
        ts[tid]  = tim[n * L + tid];
        nbs[tid] = nbr[n * L + tid];
    }
    __syncthreads();

    // gather mailbox (8B loads, 4 rows per pass)
    {
        const int lane4 = tid & 15, row4 = tid >> 4;
#pragma unroll
        for (int l0 = 0; l0 < 48; l0 += 4) {
            const int l = l0 + row4;
            const uint2 val = *((const uint2*)(src_h + nbs[l] * D) + lane4);
            *(unsigned*)&mb[l][lane4 * 4 + 0] = val.x;
            *(unsigned*)&mb[l][lane4 * 4 + 2] = val.y;
        }
        if (row4 < 2) {
            const int l = 48 + row4;
            const uint2 val = *((const uint2*)(src_h + nbs[l] * D) + lane4);
            *(unsigned*)&mb[l][lane4 * 4 + 0] = val.x;
            *(unsigned*)&mb[l][lane4 * 4 + 2] = val.y;
        }
    }

    // ranks (stable argsort∘argsort)
    if (tid < L) {
        const int t = ts[tid];
        int r = 0;
#pragma unroll 10
        for (int j = 0; j < L; j++) {
            const int tj = ts[j];
            r += (tj < t) || (tj == t && j < tid);
        }
        ro[tid] = L - 1 - r;
    }
    // argmax (first index of max)
    if (wid == 0) {
        int bv = ts[lane], bi = lane;
        if (lane + 32 < L) {
            const int v2 = ts[lane + 32];
            if (v2 > bv) { bv = v2; bi = lane + 32; }
        }
#pragma unroll
        for (int o = 16; o > 0; o >>= 1) {
            const int ov = __shfl_xor_sync(0xffffffffu, bv, o);
            const int oi = __shfl_xor_sync(0xffffffffu, bi, o);
            if (ov > bv || (ov == bv && oi < bi)) { bv = ov; bi = oi; }
        }
        if (lane == 0) s_last = bi;
    }
    __syncthreads();

    // logits
    if (tid < L) {
        const __half2* rowp  = (const __half2*)&mb[tid][0];
        const __half2* lastp = (const __half2*)&mb[s_last][0];
        float s = 0.f, s1 = 0.f;
#pragma unroll
        for (int i = 0; i < D / 2; i++) {
            const float2 m  = __half22float2(rowp[i]);
            const float2 ml = __half22float2(lastp[i]);
            s  += m.x * h[2 * i] + m.y * h[2 * i + 1];
            s1 += ml.x * m.x + ml.y * m.y;
        }
        ee[tid] = (s + qrow[ro[tid]]) * 0.125f;
        e1[tid] = s1 * 0.125f;
    }
    __syncthreads();

    // softmaxes (warp 0)
    if (wid == 0) {
        float m = -1e30f, m1 = -1e30f;
        for (int l = lane; l < L; l += 32) {
            m  = fmaxf(m,  ee[l]);
            m1 = fmaxf(m1, e1[l]);
        }
#pragma unroll
        for (int o = 16; o > 0; o >>= 1) {
            m  = fmaxf(m,  __shfl_xor_sync(0xffffffffu, m,  o));
            m1 = fmaxf(m1, __shfl_xor_sync(0xffffffffu, m1, o));
        }
        float s = 0.f, s1 = 0.f;
        for (int l = lane; l < L; l += 32) {
            const float a  = __expf(ee[l] - m);
            const float a1 = __expf(e1[l] - m1);
            ee[l] = a;  e1[l] = a1;
            s += a;  s1 += a1;
        }
#pragma unroll
        for (int o = 16; o > 0; o >>= 1) {
            s  += __shfl_xor_sync(0xffffffffu, s,  o);
            s1 += __shfl_xor_sync(0xffffffffu, s1, o);
        }
        const float inv = 1.f / s, inv1 = 1.f / s1;
        for (int l = lane; l < L; l += 32) {
            ee[l] *= inv;
            e1[l] *= inv1;
        }
    }
    __syncthreads();

    // weighted mailbox sums -> m vector
    float hl = 0.f, hs = 0.f;
#pragma unroll 10
    for (int l = 0; l < L; l++) {
        const float m = __half2float(mb[l][tid]);
        hl += ee[l] * m;
        hs += e1[l] * m;
    }
    mrow[tid]     = hl;
    mrow[D + tid] = hs;
    if (tid < L) mrow[2 * D + ro[tid]] = ee[tid];   // beta scatter
}

// ---------------------------------------------------------------------------
// epilogue: out = elu(m @ Wcat + feat). 32 nodes x 64 cols per 256-thr block.
// NI % 32 == 0, so blocks never straddle sides.
// ---------------------------------------------------------------------------
#define EPB ((NT + 31) / 32)    // 1563

__global__ __launch_bounds__(256) void epilogue(
    const float* __restrict__ user_feat, const float* __restrict__ item_feat,
    float* __restrict__ user_out,        float* __restrict__ item_out)
{
    const int nb   = blockIdx.x * 32;
    const bool item = nb < NI;
    const float* Wc = g_wcat[item ? 0 : 1];
    const float* feat = item ? item_feat : user_feat;
    float* out        = item ? item_out  : user_out;
    const int base    = item ? nb : nb - NI;   // local node base
    const int Nloc    = item ? NI : NU;

    __shared__ float mT[KM * 34];   // mT[k][node], pad 34 (8B-aligned pairs)

    const int t = threadIdx.x, lane = t & 31, w = t >> 5;

    // stage mT: warp w -> nodes w*4..w*4+3, lanes stride over k
#pragma unroll
    for (int i = 0; i < 4; i++) {
        const int nl = w * 4 + i;
        const int g  = nb + nl;
        if (g < NT) {
            const float* mr = g_m + g * KM;
            for (int k = lane; k < KM; k += 32)
                mT[k * 34 + nl] = mr[k];
        }
    }
    __syncthreads();

    const int ng = t >> 4, cg = t & 15;      // node pair group / col group
    float acc[2][4] = {{0.f,0.f,0.f,0.f},{0.f,0.f,0.f,0.f}};

#pragma unroll 2
    for (int k = 0; k < KM; k++) {
        const float2 mv = *(const float2*)&mT[k * 34 + 2 * ng];
        const float4 wv = *(const float4*)&Wc[k * D + cg * 4];
        acc[0][0] += mv.x * wv.x; acc[0][1] += mv.x * wv.y;
        acc[0][2] += mv.x * wv.z; acc[0][3] += mv.x * wv.w;
        acc[1][0] += mv.y * wv.x; acc[1][1] += mv.y * wv.y;
        acc[1][2] += mv.y * wv.z; acc[1][3] += mv.y * wv.w;
    }

#pragma unroll
    for (int i = 0; i < 2; i++) {
        const int nl = base + 2 * ng + i;
        if (nl < Nloc && nb + 2 * ng + i < NT) {
            const float4 fv = *(const float4*)&feat[nl * D + cg * 4];
            float4 r;
            r.x = acc[i][0] + fv.x;  r.x = r.x > 0.f ? r.x : expm1f(r.x);
            r.y = acc[i][1] + fv.y;  r.y = r.y > 0.f ? r.y : expm1f(r.y);
            r.z = acc[i][2] + fv.z;  r.z = r.z > 0.f ? r.z : expm1f(r.z);
            r.w = acc[i][3] + fv.w;  r.w = r.w > 0.f ? r.w : expm1f(r.w);
            *(float4*)&out[nl * D + cg * 4] = r;
        }
    }
}

// ---------------------------------------------------------------------------
extern "C" void kernel_launch(void* const* d_in, const int* in_sizes, int n_in,
                              void* d_out, int out_size) {
    const float* user_feat = (const float*)d_in[0];
    const float* item_feat = (const float*)d_in[1];
    const float* W_u       = (const float*)d_in[2];
    const float* W_i       = (const float*)d_in[3];
    const float* Wg_u      = (const float*)d_in[4];
    const float* Wg_i      = (const float*)d_in[5];
    const float* i_te      = (const float*)d_in[6];
    const float* i_te_k    = (const float*)d_in[7];
    const float* u_te      = (const float*)d_in[8];
    const float* u_te_k    = (const float*)d_in[9];
    const int*   item_nbr  = (const int*)d_in[10];
    const int*   item_time = (const int*)d_in[11];
    const int*   user_nbr  = (const int*)d_in[12];
    const int*   user_time = (const int*)d_in[13];

    float* user_out = (float*)d_out;            // [NU, D]
    float* item_out = (float*)d_out + NU * D;   // [NI, D]

    prep_wcat<<<2, 256>>>(Wg_i, i_te_k, Wg_u, u_te_k);
    proj<<<PBU + PBI, 256>>>(user_feat, item_feat, W_u, W_i);
    q_gemm<<<NBI + NBU, 256>>>(i_te, u_te);
    attn_all<<<NT, 64>>>(item_nbr, item_time, user_nbr, user_time);
    epilogue<<<EPB, 256>>>(user_feat, item_feat, user_out, item_out);
}

// round 6
// speedup vs baseline: 3.6029x; 1.0992x over previous
#include <cuda_runtime.h>
#include <cuda_fp16.h>
#include <math.h>

#define D  64
#define L  50
#define NU 30000
#define NI 20000
#define NT (NU + NI)        // 50000 total nodes
#define KM 178              // m-vector: 64 hl_mb | 64 hs | 50 beta

#define QN   64
#define NBI  ((NI + QN - 1) / QN)   // 313
#define NBU  ((NU + QN - 1) / QN)   // 469
#define PBI  ((NI + 63) / 64)       // 313
#define PBU  ((NU + 63) / 64)       // 469
#define PB   (PBU + PBI)            // proj blocks
#define QB   (NBI + NBU)            // q blocks

// device scratch (allocation-free rule)
__device__ __half g_uh[NU * D];
__device__ __half g_ih[NI * D];
__device__ float  g_q[NT * L];          // q[n][r] = dot(te[r], h_n)
__device__ float  g_m[NT * KM];         // per-node m vector
__device__ float  g_wcat[2][KM * D];    // [0]=item, [1]=user
__device__ float  g_teW[2][L * D];      // te @ W^T per side

// ---------------------------------------------------------------------------
// prep: blocks 0,1 -> Wcat = [Wg ; te_k @ Wg_top]; blocks 2,3 -> teW = te@W^T
// ---------------------------------------------------------------------------
__global__ __launch_bounds__(256) void prep(
    const float* __restrict__ Wg_i, const float* __restrict__ i_te_k,
    const float* __restrict__ Wg_u, const float* __restrict__ u_te_k,
    const float* __restrict__ i_te, const float* __restrict__ u_te,
    const float* __restrict__ W_i,  const float* __restrict__ W_u)
{
    const int t = threadIdx.x;
    __shared__ float Wsh[D * D];

    if (blockIdx.x < 2) {           // Wcat
        const int s = blockIdx.x;   // 0 item, 1 user
        const float* Wg   = s == 0 ? Wg_i : Wg_u;
        const float* te_k = s == 0 ? i_te_k : u_te_k;
        float* out = g_wcat[s];
        for (int idx = t; idx < D * D; idx += 256) Wsh[idx] = Wg[idx];
        for (int idx = t; idx < 2 * D * D; idx += 256) out[idx] = Wg[idx];
        __syncthreads();
        for (int idx = t; idx < L * D; idx += 256) {
            const int r = idx >> 6, c = idx & 63;
            float acc = 0.f;
#pragma unroll 8
            for (int d = 0; d < D; d++) acc += te_k[r * D + d] * Wsh[d * D + c];
            out[(2 * D + r) * D + c] = acc;
        }
    } else {                        // teW[r][k] = sum_d te[r,d] * W[k,d]
        const int s = blockIdx.x - 2;
        const float* te = s == 0 ? i_te : u_te;
        const float* W  = s == 0 ? W_i  : W_u;
        float* out = g_teW[s];
        for (int idx = t; idx < D * D; idx += 256) Wsh[idx] = W[idx];
        __syncthreads();
        for (int idx = t; idx < L * D; idx += 256) {
            const int r = idx >> 6, k = idx & 63;
            float acc = 0.f;
#pragma unroll 8
            for (int d = 0; d < D; d++) acc += te[r * D + d] * Wsh[k * D + d];
            out[r * D + k] = acc;
        }
    }
}

// ---------------------------------------------------------------------------
// projq: fused. blocks [0,PB): proj feat@W -> half; blocks [PB,PB+QB): q GEMM
//   q[n][r] = dot(feat[n], teW[r])   (no dependency on proj)
// ---------------------------------------------------------------------------
union SmemPQ {
    struct { float  fT[D * 68]; float  Ws[D * 68]; } p;
    struct { __half hT[D][68];  __half tT[D][56];  } q;
};

__global__ __launch_bounds__(256) void projq(
    const float* __restrict__ user_feat, const float* __restrict__ item_feat,
    const float* __restrict__ W_u,       const float* __restrict__ W_i)
{
    __shared__ SmemPQ sm;
    const int t = threadIdx.x, lane = t & 31, w = t >> 5;

    if (blockIdx.x < PB) {
        // ---------------- proj path ----------------
        const bool user = blockIdx.x < PBU;
        const int  r0   = (user ? blockIdx.x : blockIdx.x - PBU) * 64;
        const int  N    = user ? NU : NI;
        const float* feat = user ? user_feat : item_feat;
        const float* W    = user ? W_u : W_i;
        __half* outp      = user ? g_uh : g_ih;

#pragma unroll
        for (int i = 0; i < 8; i++) {
            const int r = w * 8 + i, row = r0 + r;
            float a = 0.f, b = 0.f;
            if (row < N) { a = feat[row * D + lane]; b = feat[row * D + 32 + lane]; }
            sm.p.fT[lane * 68 + r]        = a;
            sm.p.fT[(32 + lane) * 68 + r] = b;
        }
        for (int idx = t; idx < D * D; idx += 256)
            sm.p.Ws[(idx >> 6) * 68 + (idx & 63)] = W[idx];
        __syncthreads();

        const int rg = t >> 4, cg = t & 15;
        float acc[4][4];
#pragma unroll
        for (int i = 0; i < 4; i++)
#pragma unroll
            for (int j = 0; j < 4; j++) acc[i][j] = 0.f;
#pragma unroll 8
        for (int k = 0; k < D; k++) {
            const float4 fv = *(const float4*)&sm.p.fT[k * 68 + rg * 4];
            const float4 wv = *(const float4*)&sm.p.Ws[k * 68 + cg * 4];
            const float f[4]  = {fv.x, fv.y, fv.z, fv.w};
            const float wc[4] = {wv.x, wv.y, wv.z, wv.w};
#pragma unroll
            for (int i = 0; i < 4; i++)
#pragma unroll
                for (int j = 0; j < 4; j++) acc[i][j] += f[i] * wc[j];
        }
#pragma unroll
        for (int i = 0; i < 4; i++) {
            const int row = r0 + rg * 4 + i;
            if (row < N) {
                __half2 p0 = __floats2half2_rn(acc[i][0], acc[i][1]);
                __half2 p1 = __floats2half2_rn(acc[i][2], acc[i][3]);
                *(__half2*)&outp[row * D + cg * 4]     = p0;
                *(__half2*)&outp[row * D + cg * 4 + 2] = p1;
            }
        }
    } else {
        // ---------------- q path ----------------
        const int  qb   = blockIdx.x - PB;
        const bool item = qb < NBI;
        const int  n0   = (item ? qb : qb - NBI) * QN;
        const int  N    = item ? NI : NU;
        const float* feat = item ? item_feat : user_feat;
        const float* teW  = g_teW[item ? 0 : 1];
        float* qout       = g_q + (item ? 0 : NI * L);

        for (int j = w; j < QN; j += 8) {
            const int n = n0 + j;
            float a = 0.f, b = 0.f;
            if (n < N) { a = feat[n * D + lane]; b = feat[n * D + 32 + lane]; }
            sm.q.hT[lane][j]      = __float2half(a);
            sm.q.hT[32 + lane][j] = __float2half(b);
        }
        for (int r = w; r < 52; r += 8) {
            float a = 0.f, b = 0.f;
            if (r < L) { a = teW[r * D + lane]; b = teW[r * D + 32 + lane]; }
            sm.q.tT[lane][r]      = __float2half(a);
            sm.q.tT[32 + lane][r] = __float2half(b);
        }
        __syncthreads();

        if (t < 208) {
            const int nb = (t & 15) * 4;
            const int rb = (t >> 4) * 4;
            float acc[4][4];
#pragma unroll
            for (int i = 0; i < 4; i++)
#pragma unroll
                for (int j = 0; j < 4; j++) acc[i][j] = 0.f;
#pragma unroll
            for (int d = 0; d < D; d++) {
                const __half2 ha = *(const __half2*)&sm.q.hT[d][nb];
                const __half2 hb = *(const __half2*)&sm.q.hT[d][nb + 2];
                const __half2 ta = *(const __half2*)&sm.q.tT[d][rb];
                const __half2 tb = *(const __half2*)&sm.q.tT[d][rb + 2];
                const float h0 = __low2float(ha), h1 = __high2float(ha);
                const float h2 = __low2float(hb), h3 = __high2float(hb);
                const float t0 = __low2float(ta), t1 = __high2float(ta);
                const float t2 = __low2float(tb), t3 = __high2float(tb);
                acc[0][0] += h0 * t0; acc[0][1] += h0 * t1; acc[0][2] += h0 * t2; acc[0][3] += h0 * t3;
                acc[1][0] += h1 * t0; acc[1][1] += h1 * t1; acc[1][2] += h1 * t2; acc[1][3] += h1 * t3;
                acc[2][0] += h2 * t0; acc[2][1] += h2 * t1; acc[2][2] += h2 * t2; acc[2][3] += h2 * t3;
                acc[3][0] += h3 * t0; acc[3][1] += h3 * t1; acc[3][2] += h3 * t2; acc[3][3] += h3 * t3;
            }
#pragma unroll
            for (int i = 0; i < 4; i++) {
                const int n = n0 + nb + i;
                if (n < N) {
#pragma unroll
                    for (int j = 0; j < 4; j++)
                        if (rb + j < L) qout[n * L + rb + j] = acc[i][j];
                }
            }
        }
    }
}

// ---------------------------------------------------------------------------
// attn_all: gather + ranks + logits(hfma2) + softmax + weighted sums -> g_m
// ---------------------------------------------------------------------------
#define MBP 72   // row stride in halves: 144B, 16B-aligned, conflict-free

__global__ __launch_bounds__(64) void attn_all(
    const int* __restrict__ item_nbr, const int* __restrict__ item_time,
    const int* __restrict__ user_nbr, const int* __restrict__ user_time)
{
    const int b    = blockIdx.x;
    const int tid  = threadIdx.x;
    const int lane = tid & 31;
    const int wid  = tid >> 5;

    int n;
    const __half *src_h, *dst_h;
    const int *nbr, *tim;
    if (b < NI) {
        n = b;  src_h = g_uh;  dst_h = g_ih;
        nbr = item_nbr;  tim = item_time;
    } else {
        n = b - NI;  src_h = g_ih;  dst_h = g_uh;
        nbr = user_nbr;  tim = user_time;
    }
    const float* qrow = g_q + b * L;
    float* mrow = g_m + b * KM;

    __shared__ __align__(16) __half mb[L][MBP];
    __shared__ __align__(16) __half hh[D];
    __shared__ __align__(16) int    ts[52];
    __shared__ float ee[L], e1[L];
    __shared__ int   nbs[L], ro[L];
    __shared__ int   s_last;

    // ---- stage h (half), times, neighbor ids ----
    if (tid < 32) ((__half2*)hh)[tid] = ((const __half2*)(dst_h + n * D))[tid];
    if (tid < L) {
        ts[tid]  = tim[n * L + tid];
        nbs[tid] = nbr[n * L + tid];
    }
    __syncthreads();

    // ---- gather mailbox: 8B loads, 4 rows per pass ----
    {
        const int lane4 = tid & 15, row4 = tid >> 4;
#pragma unroll
        for (int l0 = 0; l0 < 48; l0 += 4) {
            const int l = l0 + row4;
            const uint2 val = *((const uint2*)(src_h + nbs[l] * D) + lane4);
            *(unsigned*)&mb[l][lane4 * 4 + 0] = val.x;
            *(unsigned*)&mb[l][lane4 * 4 + 2] = val.y;
        }
        if (row4 < 2) {
            const int l = 48 + row4;
            const uint2 val = *((const uint2*)(src_h + nbs[l] * D) + lane4);
            *(unsigned*)&mb[l][lane4 * 4 + 0] = val.x;
            *(unsigned*)&mb[l][lane4 * 4 + 2] = val.y;
        }
    }

    // ---- ranks: int4 register reads of ts (13 LDS.128 instead of 50 LDS) ----
    if (tid < L) {
        const int t = ts[tid];
        int r = 0;
#pragma unroll
        for (int jb = 0; jb < 12; jb++) {
            const int4 v = ((const int4*)ts)[jb];
            const int j = jb * 4;
            r += (v.x < t) || (v.x == t && (j + 0) < tid);
            r += (v.y < t) || (v.y == t && (j + 1) < tid);
            r += (v.z < t) || (v.z == t && (j + 2) < tid);
            r += (v.w < t) || (v.w == t && (j + 3) < tid);
        }
        {
            const int2 v = ((const int2*)ts)[24];
            r += (v.x < t) || (v.x == t && 48 < tid);
            r += (v.y < t) || (v.y == t && 49 < tid);
        }
        ro[tid] = L - 1 - r;
    }
    // ---- argmax (first index of max) in warp 0 ----
    if (wid == 0) {
        int bv = ts[lane], bi = lane;
        if (lane + 32 < L) {
            const int v2 = ts[lane + 32];
            if (v2 > bv) { bv = v2; bi = lane + 32; }
        }
#pragma unroll
        for (int o = 16; o > 0; o >>= 1) {
            const int ov = __shfl_xor_sync(0xffffffffu, bv, o);
            const int oi = __shfl_xor_sync(0xffffffffu, bi, o);
            if (ov > bv || (ov == bv && oi < bi)) { bv = ov; bi = oi; }
        }
        if (lane == 0) s_last = bi;
    }
    __syncthreads();

    // ---- logits: hfma2 on 16B LDS rows ----
    if (tid < L) {
        const uint4* rowp  = (const uint4*)&mb[tid][0];
        const uint4* lastp = (const uint4*)&mb[s_last][0];
        const uint4* hp    = (const uint4*)hh;
        __half2 sa = __float2half2_rn(0.f), sb = sa, ta = sa, tb = sa;
#pragma unroll
        for (int i = 0; i < 8; i++) {
            const uint4 rv = rowp[i], lv = lastp[i], hv = hp[i];
            const __half2 r0 = *(const __half2*)&rv.x, r1 = *(const __half2*)&rv.y;
            const __half2 r2 = *(const __half2*)&rv.z, r3 = *(const __half2*)&rv.w;
            const __half2 l0 = *(const __half2*)&lv.x, l1 = *(const __half2*)&lv.y;
            const __half2 l2 = *(const __half2*)&lv.z, l3 = *(const __half2*)&lv.w;
            const __half2 h0 = *(const __half2*)&hv.x, h1 = *(const __half2*)&hv.y;
            const __half2 h2 = *(const __half2*)&hv.z, h3 = *(const __half2*)&hv.w;
            sa = __hfma2(r0, h0, sa); sb = __hfma2(r1, h1, sb);
            sa = __hfma2(r2, h2, sa); sb = __hfma2(r3, h3, sb);
            ta = __hfma2(r0, l0, ta); tb = __hfma2(r1, l1, tb);
            ta = __hfma2(r2, l2, ta); tb = __hfma2(r3, l3, tb);
        }
        const float s  = __low2float(sa) + __high2float(sa)
                       + __low2float(sb) + __high2float(sb);
        const float s1 = __low2float(ta) + __high2float(ta)
                       + __low2float(tb) + __high2float(tb);
        ee[tid] = (s + qrow[ro[tid]]) * 0.125f;
        e1[tid] = s1 * 0.125f;
    }
    __syncthreads();

    // ---- two softmaxes over L (warp 0) ----
    if (wid == 0) {
        float m = -1e30f, m1 = -1e30f;
        for (int l = lane; l < L; l += 32) {
            m  = fmaxf(m,  ee[l]);
            m1 = fmaxf(m1, e1[l]);
        }
#pragma unroll
        for (int o = 16; o > 0; o >>= 1) {
            m  = fmaxf(m,  __shfl_xor_sync(0xffffffffu, m,  o));
            m1 = fmaxf(m1, __shfl_xor_sync(0xffffffffu, m1, o));
        }
        float s = 0.f, s1 = 0.f;
        for (int l = lane; l < L; l += 32) {
            const float a  = __expf(ee[l] - m);
            const float a1 = __expf(e1[l] - m1);
            ee[l] = a;  e1[l] = a1;
            s += a;  s1 += a1;
        }
#pragma unroll
        for (int o = 16; o > 0; o >>= 1) {
            s  += __shfl_xor_sync(0xffffffffu, s,  o);
            s1 += __shfl_xor_sync(0xffffffffu, s1, o);
        }
        const float inv = 1.f / s, inv1 = 1.f / s1;
        for (int l = lane; l < L; l += 32) {
            ee[l] *= inv;
            e1[l] *= inv1;
        }
    }
    __syncthreads();

    // ---- weighted mailbox sums -> m vector (fp32) ----
    float hl = 0.f, hs = 0.f;
#pragma unroll 10
    for (int l = 0; l < L; l++) {
        const float m = __half2float(mb[l][tid]);
        hl += ee[l] * m;
        hs += e1[l] * m;
    }
    mrow[tid]     = hl;
    mrow[D + tid] = hs;
    if (tid < L) mrow[2 * D + ro[tid]] = ee[tid];   // beta scatter
}

// ---------------------------------------------------------------------------
// epilogue: out = elu(m @ Wcat + feat). 32 nodes x 64 cols per 256-thr block.
// ---------------------------------------------------------------------------
#define EPB ((NT + 31) / 32)    // 1563

__global__ __launch_bounds__(256) void epilogue(
    const float* __restrict__ user_feat, const float* __restrict__ item_feat,
    float* __restrict__ user_out,        float* __restrict__ item_out)
{
    const int nb    = blockIdx.x * 32;
    const bool item = nb < NI;
    const float* Wc   = g_wcat[item ? 0 : 1];
    const float* feat = item ? item_feat : user_feat;
    float* out        = item ? item_out  : user_out;
    const int base    = item ? nb : nb - NI;
    const int Nloc    = item ? NI : NU;

    __shared__ float mT[KM * 34];

    const int t = threadIdx.x, lane = t & 31, w = t >> 5;

#pragma unroll
    for (int i = 0; i < 4; i++) {
        const int nl = w * 4 + i;
        const int g  = nb + nl;
        if (g < NT) {
            const float* mr = g_m + g * KM;
            for (int k = lane; k < KM; k += 32)
                mT[k * 34 + nl] = mr[k];
        }
    }
    __syncthreads();

    const int ng = t >> 4, cg = t & 15;
    float acc[2][4] = {{0.f,0.f,0.f,0.f},{0.f,0.f,0.f,0.f}};

#pragma unroll 2
    for (int k = 0; k < KM; k++) {
        const float2 mv = *(const float2*)&mT[k * 34 + 2 * ng];
        const float4 wv = *(const float4*)&Wc[k * D + cg * 4];
        acc[0][0] += mv.x * wv.x; acc[0][1] += mv.x * wv.y;
        acc[0][2] += mv.x * wv.z; acc[0][3] += mv.x * wv.w;
        acc[1][0] += mv.y * wv.x; acc[1][1] += mv.y * wv.y;
        acc[1][2] += mv.y * wv.z; acc[1][3] += mv.y * wv.w;
    }

#pragma unroll
    for (int i = 0; i < 2; i++) {
        const int nl = base + 2 * ng + i;
        if (nl < Nloc && nb + 2 * ng + i < NT) {
            const float4 fv = *(const float4*)&feat[nl * D + cg * 4];
            float4 r;
            r.x = acc[i][0] + fv.x;  r.x = r.x > 0.f ? r.x : expm1f(r.x);
            r.y = acc[i][1] + fv.y;  r.y = r.y > 0.f ? r.y : expm1f(r.y);
            r.z = acc[i][2] + fv.z;  r.z = r.z > 0.f ? r.z : expm1f(r.z);
            r.w = acc[i][3] + fv.w;  r.w = r.w > 0.f ? r.w : expm1f(r.w);
            *(float4*)&out[nl * D + cg * 4] = r;
        }
    }
}

// ---------------------------------------------------------------------------
extern "C" void kernel_launch(void* const* d_in, const int* in_sizes, int n_in,
                              void* d_out, int out_size) {
    const float* user_feat = (const float*)d_in[0];
    const float* item_feat = (const float*)d_in[1];
    const float* W_u       = (const float*)d_in[2];
    const float* W_i       = (const float*)d_in[3];
    const float* Wg_u      = (const float*)d_in[4];
    const float* Wg_i      = (const float*)d_in[5];
    const float* i_te      = (const float*)d_in[6];
    const float* i_te_k    = (const float*)d_in[7];
    const float* u_te      = (const float*)d_in[8];
    const float* u_te_k    = (const float*)d_in[9];
    const int*   item_nbr  = (const int*)d_in[10];
    const int*   item_time = (const int*)d_in[11];
    const int*   user_nbr  = (const int*)d_in[12];
    const int*   user_time = (const int*)d_in[13];

    float* user_out = (float*)d_out;            // [NU, D]
    float* item_out = (float*)d_out + NU * D;   // [NI, D]

    prep<<<4, 256>>>(Wg_i, i_te_k, Wg_u, u_te_k, i_te, u_te, W_i, W_u);
    projq<<<PB + QB, 256>>>(user_feat, item_feat, W_u, W_i);
    attn_all<<<NT, 64>>>(item_nbr, item_time, user_nbr, user_time);
    epilogue<<<EPB, 256>>>(user_feat, item_feat, user_out, item_out);
}

// round 7
// speedup vs baseline: 4.1997x; 1.1657x over previous
#include <cuda_runtime.h>
#include <cuda_fp16.h>
#include <mma.h>
#include <math.h>

using namespace nvcuda;

#define D  64
#define L  50
#define NU 30000
#define NI 20000
#define NT (NU + NI)        // 50000 total nodes
#define KMP 192             // padded m-vector: 64 hl | 64 hs | 50 beta | 14 zero

#define QN   64
#define NBI  ((NI + QN - 1) / QN)   // 313
#define NBU  ((NU + QN - 1) / QN)   // 469
#define PBI  ((NI + 63) / 64)       // 313
#define PBU  ((NU + 63) / 64)       // 469
#define PB   (PBU + PBI)
#define QB   (NBI + NBU)
#define EIB  ((NI + 63) / 64)       // 313 epilogue item blocks
#define EUB  ((NU + 63) / 64)       // 469 epilogue user blocks

// device scratch (allocation-free rule; statically zero-initialized)
__device__ __half g_uh[NU * D];
__device__ __half g_ih[NI * D];
__device__ float  g_q[NT * L];              // q[n][r] = dot(te[r], h_n)
__device__ __half g_m[(NT + 64) * KMP];     // per-node m vector (fp16, padded)
__device__ __half g_wch[2][KMP * D];        // fp16 Wcat: [Wg ; te_k@Wg_top ; 0]
__device__ float  g_teW[2][L * D];          // te @ W^T per side

// ---------------------------------------------------------------------------
// prep: blocks 0,1 -> Wcat(half); blocks 2,3 -> teW = te @ W^T
// ---------------------------------------------------------------------------
__global__ __launch_bounds__(256) void prep(
    const float* __restrict__ Wg_i, const float* __restrict__ i_te_k,
    const float* __restrict__ Wg_u, const float* __restrict__ u_te_k,
    const float* __restrict__ i_te, const float* __restrict__ u_te,
    const float* __restrict__ W_i,  const float* __restrict__ W_u)
{
    const int t = threadIdx.x;
    __shared__ float Wsh[D * D];

    if (blockIdx.x < 2) {           // Wcat (fp16)
        const int s = blockIdx.x;   // 0 item, 1 user
        const float* Wg   = s == 0 ? Wg_i : Wg_u;
        const float* te_k = s == 0 ? i_te_k : u_te_k;
        __half* out = g_wch[s];
        for (int idx = t; idx < D * D; idx += 256) Wsh[idx] = Wg[idx];
        for (int idx = t; idx < 2 * D * D; idx += 256)
            out[idx] = __float2half(Wg[idx]);               // rows 0..127
        for (int idx = t; idx < (KMP - 2 * D - L) * D; idx += 256)
            out[(2 * D + L) * D + idx] = __half(0.f);       // rows 178..191
        __syncthreads();
        for (int idx = t; idx < L * D; idx += 256) {        // rows 128..177
            const int r = idx >> 6, c = idx & 63;
            float acc = 0.f;
#pragma unroll 8
            for (int d = 0; d < D; d++) acc += te_k[r * D + d] * Wsh[d * D + c];
            out[(2 * D + r) * D + c] = __float2half(acc);
        }
    } else {                        // teW[r][k] = sum_d te[r,d] * W[k,d]
        const int s = blockIdx.x - 2;
        const float* te = s == 0 ? i_te : u_te;
        const float* W  = s == 0 ? W_i  : W_u;
        float* out = g_teW[s];
        for (int idx = t; idx < D * D; idx += 256) Wsh[idx] = W[idx];
        __syncthreads();
        for (int idx = t; idx < L * D; idx += 256) {
            const int r = idx >> 6, k = idx & 63;
            float acc = 0.f;
#pragma unroll 8
            for (int d = 0; d < D; d++) acc += te[r * D + d] * Wsh[k * D + d];
            out[r * D + k] = acc;
        }
    }
}

// ---------------------------------------------------------------------------
// projq: fused. blocks [0,PB): proj feat@W -> half; blocks [PB,PB+QB): q GEMM
// ---------------------------------------------------------------------------
union SmemPQ {
    struct { float  fT[D * 68]; float  Ws[D * 68]; } p;
    struct { __half hT[D][68];  __half tT[D][56];  } q;
};

__global__ __launch_bounds__(256) void projq(
    const float* __restrict__ user_feat, const float* __restrict__ item_feat,
    const float* __restrict__ W_u,       const float* __restrict__ W_i)
{
    __shared__ SmemPQ sm;
    const int t = threadIdx.x, lane = t & 31, w = t >> 5;

    if (blockIdx.x < PB) {
        // ---------------- proj path ----------------
        const bool user = blockIdx.x < PBU;
        const int  r0   = (user ? blockIdx.x : blockIdx.x - PBU) * 64;
        const int  N    = user ? NU : NI;
        const float* feat = user ? user_feat : item_feat;
        const float* W    = user ? W_u : W_i;
        __half* outp      = user ? g_uh : g_ih;

#pragma unroll
        for (int i = 0; i < 8; i++) {
            const int r = w * 8 + i, row = r0 + r;
            float a = 0.f, b = 0.f;
            if (row < N) { a = feat[row * D + lane]; b = feat[row * D + 32 + lane]; }
            sm.p.fT[lane * 68 + r]        = a;
            sm.p.fT[(32 + lane) * 68 + r] = b;
        }
        for (int idx = t; idx < D * D; idx += 256)
            sm.p.Ws[(idx >> 6) * 68 + (idx & 63)] = W[idx];
        __syncthreads();

        const int rg = t >> 4, cg = t & 15;
        float acc[4][4];
#pragma unroll
        for (int i = 0; i < 4; i++)
#pragma unroll
            for (int j = 0; j < 4; j++) acc[i][j] = 0.f;
#pragma unroll 8
        for (int k = 0; k < D; k++) {
            const float4 fv = *(const float4*)&sm.p.fT[k * 68 + rg * 4];
            const float4 wv = *(const float4*)&sm.p.Ws[k * 68 + cg * 4];
            const float f[4]  = {fv.x, fv.y, fv.z, fv.w};
            const float wc[4] = {wv.x, wv.y, wv.z, wv.w};
#pragma unroll
            for (int i = 0; i < 4; i++)
#pragma unroll
                for (int j = 0; j < 4; j++) acc[i][j] += f[i] * wc[j];
        }
#pragma unroll
        for (int i = 0; i < 4; i++) {
            const int row = r0 + rg * 4 + i;
            if (row < N) {
                __half2 p0 = __floats2half2_rn(acc[i][0], acc[i][1]);
                __half2 p1 = __floats2half2_rn(acc[i][2], acc[i][3]);
                *(__half2*)&outp[row * D + cg * 4]     = p0;
                *(__half2*)&outp[row * D + cg * 4 + 2] = p1;
            }
        }
    } else {
        // ---------------- q path ----------------
        const int  qb   = blockIdx.x - PB;
        const bool item = qb < NBI;
        const int  n0   = (item ? qb : qb - NBI) * QN;
        const int  N    = item ? NI : NU;
        const float* feat = item ? item_feat : user_feat;
        const float* teW  = g_teW[item ? 0 : 1];
        float* qout       = g_q + (item ? 0 : NI * L);

        for (int j = w; j < QN; j += 8) {
            const int n = n0 + j;
            float a = 0.f, b = 0.f;
            if (n < N) { a = feat[n * D + lane]; b = feat[n * D + 32 + lane]; }
            sm.q.hT[lane][j]      = __float2half(a);
            sm.q.hT[32 + lane][j] = __float2half(b);
        }
        for (int r = w; r < 52; r += 8) {
            float a = 0.f, b = 0.f;
            if (r < L) { a = teW[r * D + lane]; b = teW[r * D + 32 + lane]; }
            sm.q.tT[lane][r]      = __float2half(a);
            sm.q.tT[32 + lane][r] = __float2half(b);
        }
        __syncthreads();

        if (t < 208) {
            const int nb = (t & 15) * 4;
            const int rb = (t >> 4) * 4;
            float acc[4][4];
#pragma unroll
            for (int i = 0; i < 4; i++)
#pragma unroll
                for (int j = 0; j < 4; j++) acc[i][j] = 0.f;
#pragma unroll
            for (int d = 0; d < D; d++) {
                const __half2 ha = *(const __half2*)&sm.q.hT[d][nb];
                const __half2 hb = *(const __half2*)&sm.q.hT[d][nb + 2];
                const __half2 ta = *(const __half2*)&sm.q.tT[d][rb];
                const __half2 tb = *(const __half2*)&sm.q.tT[d][rb + 2];
                const float h0 = __low2float(ha), h1 = __high2float(ha);
                const float h2 = __low2float(hb), h3 = __high2float(hb);
                const float t0 = __low2float(ta), t1 = __high2float(ta);
                const float t2 = __low2float(tb), t3 = __high2float(tb);
                acc[0][0] += h0 * t0; acc[0][1] += h0 * t1; acc[0][2] += h0 * t2; acc[0][3] += h0 * t3;
                acc[1][0] += h1 * t0; acc[1][1] += h1 * t1; acc[1][2] += h1 * t2; acc[1][3] += h1 * t3;
                acc[2][0] += h2 * t0; acc[2][1] += h2 * t1; acc[2][2] += h2 * t2; acc[2][3] += h2 * t3;
                acc[3][0] += h3 * t0; acc[3][1] += h3 * t1; acc[3][2] += h3 * t2; acc[3][3] += h3 * t3;
            }
#pragma unroll
            for (int i = 0; i < 4; i++) {
                const int n = n0 + nb + i;
                if (n < N) {
#pragma unroll
                    for (int j = 0; j < 4; j++)
                        if (rb + j < L) qout[n * L + rb + j] = acc[i][j];
                }
            }
        }
    }
}

// ---------------------------------------------------------------------------
// attn_all: gather + ranks + logits(hfma2) + softmax + weighted sums -> g_m
// ---------------------------------------------------------------------------
#define MBP 72

__global__ __launch_bounds__(64) void attn_all(
    const int* __restrict__ item_nbr, const int* __restrict__ item_time,
    const int* __restrict__ user_nbr, const int* __restrict__ user_time)
{
    const int b    = blockIdx.x;
    const int tid  = threadIdx.x;
    const int lane = tid & 31;
    const int wid  = tid >> 5;

    int n;
    const __half *src_h, *dst_h;
    const int *nbr, *tim;
    if (b < NI) {
        n = b;  src_h = g_uh;  dst_h = g_ih;
        nbr = item_nbr;  tim = item_time;
    } else {
        n = b - NI;  src_h = g_ih;  dst_h = g_uh;
        nbr = user_nbr;  tim = user_time;
    }
    const float* qrow = g_q + b * L;
    __half* mrow = g_m + b * KMP;

    __shared__ __align__(16) __half mb[L][MBP];
    __shared__ __align__(16) __half hh[D];
    __shared__ __align__(16) int    ts[52];
    __shared__ float ee[L], e1[L];
    __shared__ int   nbs[L], ro[L];
    __shared__ int   s_last;

    if (tid < 32) ((__half2*)hh)[tid] = ((const __half2*)(dst_h + n * D))[tid];
    if (tid < L) {
        ts[tid]  = tim[n * L + tid];
        nbs[tid] = nbr[n * L + tid];
    }
    __syncthreads();

    // gather mailbox (8B loads, 4 rows per pass)
    {
        const int lane4 = tid & 15, row4 = tid >> 4;
#pragma unroll
        for (int l0 = 0; l0 < 48; l0 += 4) {
            const int l = l0 + row4;
            const uint2 val = *((const uint2*)(src_h + nbs[l] * D) + lane4);
            *(unsigned*)&mb[l][lane4 * 4 + 0] = val.x;
            *(unsigned*)&mb[l][lane4 * 4 + 2] = val.y;
        }
        if (row4 < 2) {
            const int l = 48 + row4;
            const uint2 val = *((const uint2*)(src_h + nbs[l] * D) + lane4);
            *(unsigned*)&mb[l][lane4 * 4 + 0] = val.x;
            *(unsigned*)&mb[l][lane4 * 4 + 2] = val.y;
        }
    }

    // ranks via int4 register reads of ts
    if (tid < L) {
        const int t = ts[tid];
        int r = 0;
#pragma unroll
        for (int jb = 0; jb < 12; jb++) {
            const int4 v = ((const int4*)ts)[jb];
            const int j = jb * 4;
            r += (v.x < t) || (v.x == t && (j + 0) < tid);
            r += (v.y < t) || (v.y == t && (j + 1) < tid);
            r += (v.z < t) || (v.z == t && (j + 2) < tid);
            r += (v.w < t) || (v.w == t && (j + 3) < tid);
        }
        {
            const int2 v = ((const int2*)ts)[24];
            r += (v.x < t) || (v.x == t && 48 < tid);
            r += (v.y < t) || (v.y == t && 49 < tid);
        }
        ro[tid] = L - 1 - r;
    }
    // argmax (first index of max)
    if (wid == 0) {
        int bv = ts[lane], bi = lane;
        if (lane + 32 < L) {
            const int v2 = ts[lane + 32];
            if (v2 > bv) { bv = v2; bi = lane + 32; }
        }
#pragma unroll
        for (int o = 16; o > 0; o >>= 1) {
            const int ov = __shfl_xor_sync(0xffffffffu, bv, o);
            const int oi = __shfl_xor_sync(0xffffffffu, bi, o);
            if (ov > bv || (ov == bv && oi < bi)) { bv = ov; bi = oi; }
        }
        if (lane == 0) s_last = bi;
    }
    __syncthreads();

    // logits: hfma2 on 16B LDS rows
    if (tid < L) {
        const uint4* rowp  = (const uint4*)&mb[tid][0];
        const uint4* lastp = (const uint4*)&mb[s_last][0];
        const uint4* hp    = (const uint4*)hh;
        __half2 sa = __float2half2_rn(0.f), sb = sa, ta = sa, tb = sa;
#pragma unroll
        for (int i = 0; i < 8; i++) {
            const uint4 rv = rowp[i], lv = lastp[i], hv = hp[i];
            const __half2 r0 = *(const __half2*)&rv.x, r1 = *(const __half2*)&rv.y;
            const __half2 r2 = *(const __half2*)&rv.z, r3 = *(const __half2*)&rv.w;
            const __half2 l0 = *(const __half2*)&lv.x, l1 = *(const __half2*)&lv.y;
            const __half2 l2 = *(const __half2*)&lv.z, l3 = *(const __half2*)&lv.w;
            const __half2 h0 = *(const __half2*)&hv.x, h1 = *(const __half2*)&hv.y;
            const __half2 h2 = *(const __half2*)&hv.z, h3 = *(const __half2*)&hv.w;
            sa = __hfma2(r0, h0, sa); sb = __hfma2(r1, h1, sb);
            sa = __hfma2(r2, h2, sa); sb = __hfma2(r3, h3, sb);
            ta = __hfma2(r0, l0, ta); tb = __hfma2(r1, l1, tb);
            ta = __hfma2(r2, l2, ta); tb = __hfma2(r3, l3, tb);
        }
        const float s  = __low2float(sa) + __high2float(sa)
                       + __low2float(sb) + __high2float(sb);
        const float s1 = __low2float(ta) + __high2float(ta)
                       + __low2float(tb) + __high2float(tb);
        ee[tid] = (s + qrow[ro[tid]]) * 0.125f;
        e1[tid] = s1 * 0.125f;
    }
    __syncthreads();

    // two softmaxes over L (warp 0)
    if (wid == 0) {
        float m = -1e30f, m1 = -1e30f;
        for (int l = lane; l < L; l += 32) {
            m  = fmaxf(m,  ee[l]);
            m1 = fmaxf(m1, e1[l]);
        }
#pragma unroll
        for (int o = 16; o > 0; o >>= 1) {
            m  = fmaxf(m,  __shfl_xor_sync(0xffffffffu, m,  o));
            m1 = fmaxf(m1, __shfl_xor_sync(0xffffffffu, m1, o));
        }
        float s = 0.f, s1 = 0.f;
        for (int l = lane; l < L; l += 32) {
            const float a  = __expf(ee[l] - m);
            const float a1 = __expf(e1[l] - m1);
            ee[l] = a;  e1[l] = a1;
            s += a;  s1 += a1;
        }
#pragma unroll
        for (int o = 16; o > 0; o >>= 1) {
            s  += __shfl_xor_sync(0xffffffffu, s,  o);
            s1 += __shfl_xor_sync(0xffffffffu, s1, o);
        }
        const float inv = 1.f / s, inv1 = 1.f / s1;
        for (int l = lane; l < L; l += 32) {
            ee[l] *= inv;
            e1[l] *= inv1;
        }
    }
    __syncthreads();

    // weighted mailbox sums -> fp16 m vector
    float hl = 0.f, hs = 0.f;
#pragma unroll 10
    for (int l = 0; l < L; l++) {
        const float m = __half2float(mb[l][tid]);
        hl += ee[l] * m;
        hs += e1[l] * m;
    }
    mrow[tid]     = __float2half(hl);
    mrow[D + tid] = __float2half(hs);
    if (tid < L) mrow[2 * D + ro[tid]] = __float2half(ee[tid]);
    if (tid < KMP - 2 * D - L) mrow[2 * D + L + tid] = __half(0.f);
}

// ---------------------------------------------------------------------------
// epilogue (HMMA): out = elu(m(fp16) @ Wcat(fp16) + feat).
// 64 nodes x 64 cols per 256-thread block; 8 warps x two 16x16 tiles;
// 12 k-steps of wmma 16x16x16, fragments loaded straight from global (L1-hot).
// ---------------------------------------------------------------------------
__global__ __launch_bounds__(256) void epilogue(
    const float* __restrict__ user_feat, const float* __restrict__ item_feat,
    float* __restrict__ user_out,        float* __restrict__ item_out)
{
    const bool item = blockIdx.x < EIB;
    const int  nb   = item ? blockIdx.x * 64 : NI + (blockIdx.x - EIB) * 64;
    const __half* Wc  = g_wch[item ? 0 : 1];
    const float* feat = item ? item_feat : user_feat;
    float* out        = item ? item_out  : user_out;
    const int base    = item ? nb : nb - NI;
    const int Nloc    = item ? NI : NU;

    __shared__ float ot[64 * 72];

    const int t = threadIdx.x, w = t >> 5;
    const int rt  = w >> 1;          // row tile 0..3
    const int ct0 = (w & 1) * 2;     // col tiles ct0, ct0+1

    wmma::fragment<wmma::accumulator, 16, 16, 16, float> acc0, acc1;
    wmma::fill_fragment(acc0, 0.f);
    wmma::fill_fragment(acc1, 0.f);

    const __half* abase = g_m + (size_t)(nb + rt * 16) * KMP;
#pragma unroll
    for (int kt = 0; kt < KMP / 16; kt++) {
        wmma::fragment<wmma::matrix_a, 16, 16, 16, __half, wmma::row_major> af;
        wmma::load_matrix_sync(af, abase + kt * 16, KMP);
        wmma::fragment<wmma::matrix_b, 16, 16, 16, __half, wmma::row_major> bf;
        wmma::load_matrix_sync(bf, Wc + kt * 16 * D + ct0 * 16, D);
        wmma::mma_sync(acc0, af, bf, acc0);
        wmma::load_matrix_sync(bf, Wc + kt * 16 * D + (ct0 + 1) * 16, D);
        wmma::mma_sync(acc1, af, bf, acc1);
    }
    wmma::store_matrix_sync(&ot[(rt * 16) * 72 + ct0 * 16],       acc0, 72, wmma::mem_row_major);
    wmma::store_matrix_sync(&ot[(rt * 16) * 72 + (ct0 + 1) * 16], acc1, 72, wmma::mem_row_major);
    __syncthreads();

    // residual + ELU, vectorized
    const int col = (t & 15) * 4, r0 = t >> 4;
#pragma unroll
    for (int i = 0; i < 4; i++) {
        const int row = r0 + i * 16;
        const int nl  = base + row;
        if (nl < Nloc) {
            const float4 fv = *(const float4*)&feat[nl * D + col];
            const float4 av = *(const float4*)&ot[row * 72 + col];
            float4 r;
            r.x = av.x + fv.x;  r.x = r.x > 0.f ? r.x : expm1f(r.x);
            r.y = av.y + fv.y;  r.y = r.y > 0.f ? r.y : expm1f(r.y);
            r.z = av.z + fv.z;  r.z = r.z > 0.f ? r.z : expm1f(r.z);
            r.w = av.w + fv.w;  r.w = r.w > 0.f ? r.w : expm1f(r.w);
            *(float4*)&out[nl * D + col] = r;
        }
    }
}

// ---------------------------------------------------------------------------
extern "C" void kernel_launch(void* const* d_in, const int* in_sizes, int n_in,
                              void* d_out, int out_size) {
    const float* user_feat = (const float*)d_in[0];
    const float* item_feat = (const float*)d_in[1];
    const float* W_u       = (const float*)d_in[2];
    const float* W_i       = (const float*)d_in[3];
    const float* Wg_u      = (const float*)d_in[4];
    const float* Wg_i      = (const float*)d_in[5];
    const float* i_te      = (const float*)d_in[6];
    const float* i_te_k    = (const float*)d_in[7];
    const float* u_te      = (const float*)d_in[8];
    const float* u_te_k    = (const float*)d_in[9];
    const int*   item_nbr  = (const int*)d_in[10];
    const int*   item_time = (const int*)d_in[11];
    const int*   user_nbr  = (const int*)d_in[12];
    const int*   user_time = (const int*)d_in[13];

    float* user_out = (float*)d_out;            // [NU, D]
    float* item_out = (float*)d_out + NU * D;   // [NI, D]

    prep<<<4, 256>>>(Wg_i, i_te_k, Wg_u, u_te_k, i_te, u_te, W_i, W_u);
    projq<<<PB + QB, 256>>>(user_feat, item_feat, W_u, W_i);
    attn_all<<<NT, 64>>>(item_nbr, item_time, user_nbr, user_time);
    epilogue<<<EIB + EUB, 256>>>(user_feat, item_feat, user_out, item_out);
}

// round 8
// speedup vs baseline: 4.9423x; 1.1768x over previous
#include <cuda_runtime.h>
#include <cuda_fp16.h>
#include <mma.h>
#include <math.h>

using namespace nvcuda;

#define D  64
#define L  50
#define NU 30000
#define NI 20000
#define NT (NU + NI)        // 50000 total nodes
#define KMP 192             // padded m-vector: 64 hl | 64 hs | 50 beta | 14 zero

#define QN   64
#define NBI  ((NI + QN - 1) / QN)   // 313
#define NBU  ((NU + QN - 1) / QN)   // 469
#define PBI  ((NI + 63) / 64)       // 313
#define PBU  ((NU + 63) / 64)       // 469
#define PB   (PBU + PBI)
#define QB   (NBI + NBU)
#define EIB  ((NI + 63) / 64)       // 313 epilogue item blocks
#define EUB  ((NU + 63) / 64)       // 469 epilogue user blocks

// device scratch (allocation-free rule; statically zero-initialized)
__device__ __half g_uh[NU * D];
__device__ __half g_ih[NI * D];
__device__ float  g_q[NT * L];              // q[n][r] = dot(te[r], h_n)
__device__ __half g_m[(NT + 64) * KMP];     // per-node m vector (fp16, padded)
__device__ __half g_wch[2][KMP * D];        // fp16 Wcat: [Wg ; te_k@Wg_top ; 0]
__device__ float  g_teW[2][L * D];          // te @ W^T per side

// ---------------------------------------------------------------------------
// prep: blocks 0,1 -> Wcat(half); blocks 2,3 -> teW = te @ W^T
// ---------------------------------------------------------------------------
__global__ __launch_bounds__(256) void prep(
    const float* __restrict__ Wg_i, const float* __restrict__ i_te_k,
    const float* __restrict__ Wg_u, const float* __restrict__ u_te_k,
    const float* __restrict__ i_te, const float* __restrict__ u_te,
    const float* __restrict__ W_i,  const float* __restrict__ W_u)
{
    const int t = threadIdx.x;
    __shared__ float Wsh[D * D];

    if (blockIdx.x < 2) {           // Wcat (fp16)
        const int s = blockIdx.x;   // 0 item, 1 user
        const float* Wg   = s == 0 ? Wg_i : Wg_u;
        const float* te_k = s == 0 ? i_te_k : u_te_k;
        __half* out = g_wch[s];
        for (int idx = t; idx < D * D; idx += 256) Wsh[idx] = Wg[idx];
        for (int idx = t; idx < 2 * D * D; idx += 256)
            out[idx] = __float2half(Wg[idx]);               // rows 0..127
        for (int idx = t; idx < (KMP - 2 * D - L) * D; idx += 256)
            out[(2 * D + L) * D + idx] = __half(0.f);       // rows 178..191
        __syncthreads();
        for (int idx = t; idx < L * D; idx += 256) {        // rows 128..177
            const int r = idx >> 6, c = idx & 63;
            float acc = 0.f;
#pragma unroll 8
            for (int d = 0; d < D; d++) acc += te_k[r * D + d] * Wsh[d * D + c];
            out[(2 * D + r) * D + c] = __float2half(acc);
        }
    } else {                        // teW[r][k] = sum_d te[r,d] * W[k,d]
        const int s = blockIdx.x - 2;
        const float* te = s == 0 ? i_te : u_te;
        const float* W  = s == 0 ? W_i  : W_u;
        float* out = g_teW[s];
        for (int idx = t; idx < D * D; idx += 256) Wsh[idx] = W[idx];
        __syncthreads();
        for (int idx = t; idx < L * D; idx += 256) {
            const int r = idx >> 6, k = idx & 63;
            float acc = 0.f;
#pragma unroll 8
            for (int d = 0; d < D; d++) acc += te[r * D + d] * Wsh[k * D + d];
            out[r * D + k] = acc;
        }
    }
}

// ---------------------------------------------------------------------------
// projq: fused. blocks [0,PB): proj feat@W -> half; blocks [PB,PB+QB): q GEMM
// ---------------------------------------------------------------------------
union SmemPQ {
    struct { float  fT[D * 68]; float  Ws[D * 68]; } p;
    struct { __half hT[D][68];  __half tT[D][56];  } q;
};

__global__ __launch_bounds__(256) void projq(
    const float* __restrict__ user_feat, const float* __restrict__ item_feat,
    const float* __restrict__ W_u,       const float* __restrict__ W_i)
{
    __shared__ SmemPQ sm;
    const int t = threadIdx.x, lane = t & 31, w = t >> 5;

    if (blockIdx.x < PB) {
        // ---------------- proj path ----------------
        const bool user = blockIdx.x < PBU;
        const int  r0   = (user ? blockIdx.x : blockIdx.x - PBU) * 64;
        const int  N    = user ? NU : NI;
        const float* feat = user ? user_feat : item_feat;
        const float* W    = user ? W_u : W_i;
        __half* outp      = user ? g_uh : g_ih;

#pragma unroll
        for (int i = 0; i < 8; i++) {
            const int r = w * 8 + i, row = r0 + r;
            float a = 0.f, b = 0.f;
            if (row < N) { a = feat[row * D + lane]; b = feat[row * D + 32 + lane]; }
            sm.p.fT[lane * 68 + r]        = a;
            sm.p.fT[(32 + lane) * 68 + r] = b;
        }
        for (int idx = t; idx < D * D; idx += 256)
            sm.p.Ws[(idx >> 6) * 68 + (idx & 63)] = W[idx];
        __syncthreads();

        const int rg = t >> 4, cg = t & 15;
        float acc[4][4];
#pragma unroll
        for (int i = 0; i < 4; i++)
#pragma unroll
            for (int j = 0; j < 4; j++) acc[i][j] = 0.f;
#pragma unroll 8
        for (int k = 0; k < D; k++) {
            const float4 fv = *(const float4*)&sm.p.fT[k * 68 + rg * 4];
            const float4 wv = *(const float4*)&sm.p.Ws[k * 68 + cg * 4];
            const float f[4]  = {fv.x, fv.y, fv.z, fv.w};
            const float wc[4] = {wv.x, wv.y, wv.z, wv.w};
#pragma unroll
            for (int i = 0; i < 4; i++)
#pragma unroll
                for (int j = 0; j < 4; j++) acc[i][j] += f[i] * wc[j];
        }
#pragma unroll
        for (int i = 0; i < 4; i++) {
            const int row = r0 + rg * 4 + i;
            if (row < N) {
                __half2 p0 = __floats2half2_rn(acc[i][0], acc[i][1]);
                __half2 p1 = __floats2half2_rn(acc[i][2], acc[i][3]);
                *(__half2*)&outp[row * D + cg * 4]     = p0;
                *(__half2*)&outp[row * D + cg * 4 + 2] = p1;
            }
        }
    } else {
        // ---------------- q path ----------------
        const int  qb   = blockIdx.x - PB;
        const bool item = qb < NBI;
        const int  n0   = (item ? qb : qb - NBI) * QN;
        const int  N    = item ? NI : NU;
        const float* feat = item ? item_feat : user_feat;
        const float* teW  = g_teW[item ? 0 : 1];
        float* qout       = g_q + (item ? 0 : NI * L);

        for (int j = w; j < QN; j += 8) {
            const int n = n0 + j;
            float a = 0.f, b = 0.f;
            if (n < N) { a = feat[n * D + lane]; b = feat[n * D + 32 + lane]; }
            sm.q.hT[lane][j]      = __float2half(a);
            sm.q.hT[32 + lane][j] = __float2half(b);
        }
        for (int r = w; r < 52; r += 8) {
            float a = 0.f, b = 0.f;
            if (r < L) { a = teW[r * D + lane]; b = teW[r * D + 32 + lane]; }
            sm.q.tT[lane][r]      = __float2half(a);
            sm.q.tT[32 + lane][r] = __float2half(b);
        }
        __syncthreads();

        if (t < 208) {
            const int nb = (t & 15) * 4;
            const int rb = (t >> 4) * 4;
            float acc[4][4];
#pragma unroll
            for (int i = 0; i < 4; i++)
#pragma unroll
                for (int j = 0; j < 4; j++) acc[i][j] = 0.f;
#pragma unroll
            for (int d = 0; d < D; d++) {
                const __half2 ha = *(const __half2*)&sm.q.hT[d][nb];
                const __half2 hb = *(const __half2*)&sm.q.hT[d][nb + 2];
                const __half2 ta = *(const __half2*)&sm.q.tT[d][rb];
                const __half2 tb = *(const __half2*)&sm.q.tT[d][rb + 2];
                const float h0 = __low2float(ha), h1 = __high2float(ha);
                const float h2 = __low2float(hb), h3 = __high2float(hb);
                const float t0 = __low2float(ta), t1 = __high2float(ta);
                const float t2 = __low2float(tb), t3 = __high2float(tb);
                acc[0][0] += h0 * t0; acc[0][1] += h0 * t1; acc[0][2] += h0 * t2; acc[0][3] += h0 * t3;
                acc[1][0] += h1 * t0; acc[1][1] += h1 * t1; acc[1][2] += h1 * t2; acc[1][3] += h1 * t3;
                acc[2][0] += h2 * t0; acc[2][1] += h2 * t1; acc[2][2] += h2 * t2; acc[2][3] += h2 * t3;
                acc[3][0] += h3 * t0; acc[3][1] += h3 * t1; acc[3][2] += h3 * t2; acc[3][3] += h3 * t3;
            }
#pragma unroll
            for (int i = 0; i < 4; i++) {
                const int n = n0 + nb + i;
                if (n < N) {
#pragma unroll
                    for (int j = 0; j < 4; j++)
                        if (rb + j < L) qout[n * L + rb + j] = acc[i][j];
                }
            }
        }
    }
}

// ---------------------------------------------------------------------------
// attn_all: gather + packed-key ranks + hfma2 logits + softmax + half2 sums
// ---------------------------------------------------------------------------
#define MBP 72

__global__ __launch_bounds__(64) void attn_all(
    const int* __restrict__ item_nbr, const int* __restrict__ item_time,
    const int* __restrict__ user_nbr, const int* __restrict__ user_time)
{
    const int b    = blockIdx.x;
    const int tid  = threadIdx.x;
    const int lane = tid & 31;
    const int wid  = tid >> 5;

    int n;
    const __half *src_h, *dst_h;
    const int *nbr, *tim;
    if (b < NI) {
        n = b;  src_h = g_uh;  dst_h = g_ih;
        nbr = item_nbr;  tim = item_time;
    } else {
        n = b - NI;  src_h = g_ih;  dst_h = g_uh;
        nbr = user_nbr;  tim = user_time;
    }
    const float* qrow = g_q + b * L;
    __half* mrow = g_m + b * KMP;

    __shared__ __align__(16) __half mb[L][MBP];
    __shared__ __align__(16) __half hh[D];
    __shared__ __align__(16) int    ks[64];     // packed keys: time*64 + idx
    __shared__ float   ee[L], e1[L];
    __shared__ __half2 eep[L], e1p[L];          // duplicated-alpha pairs
    __shared__ int     nbs[L], ro[L];
    __shared__ int     s_last;

    if (tid < 32) ((__half2*)hh)[tid] = ((const __half2*)(dst_h + n * D))[tid];
    if (tid < L) {
        ks[tid]  = tim[n * L + tid] * 64 + tid;
        nbs[tid] = nbr[n * L + tid];
    } else {
        ks[tid] = 0x7fffffff;                   // pad: counts as >= any key
    }
    __syncthreads();

    // gather mailbox (8B loads, 8B stores, 4 rows per pass)
    {
        const int lane4 = tid & 15, row4 = tid >> 4;
#pragma unroll
        for (int l0 = 0; l0 < 48; l0 += 4) {
            const int l = l0 + row4;
            const uint2 val = *((const uint2*)(src_h + nbs[l] * D) + lane4);
            *(uint2*)&mb[l][lane4 * 4] = val;
        }
        if (row4 < 2) {
            const int l = 48 + row4;
            const uint2 val = *((const uint2*)(src_h + nbs[l] * D) + lane4);
            *(uint2*)&mb[l][lane4 * 4] = val;
        }
    }

    // ranks: packed keys, strict < == stable (time, idx) order
    if (tid < L) {
        const int k = ks[tid];
        int r = 0;
#pragma unroll
        for (int jb = 0; jb < 13; jb++) {
            const int4 v = ((const int4*)ks)[jb];
            r += (v.x < k) + (v.y < k) + (v.z < k) + (v.w < k);
        }
        ro[tid] = L - 1 - r;
    }
    // argmax (first index of max): max of key^63 flips tie-break to lowest idx
    if (wid == 0) {
        int bv = ks[lane] ^ 63;
        if (lane < L - 32) bv = max(bv, ks[lane + 32] ^ 63);
#pragma unroll
        for (int o = 16; o > 0; o >>= 1)
            bv = max(bv, __shfl_xor_sync(0xffffffffu, bv, o));
        if (lane == 0) s_last = (bv & 63) ^ 63;
    }
    __syncthreads();

    // logits: hfma2 on 16B LDS rows
    if (tid < L) {
        const uint4* rowp  = (const uint4*)&mb[tid][0];
        const uint4* lastp = (const uint4*)&mb[s_last][0];
        const uint4* hp    = (const uint4*)hh;
        __half2 sa = __float2half2_rn(0.f), sb = sa, ta = sa, tb = sa;
#pragma unroll
        for (int i = 0; i < 8; i++) {
            const uint4 rv = rowp[i], lv = lastp[i], hv = hp[i];
            const __half2 r0 = *(const __half2*)&rv.x, r1 = *(const __half2*)&rv.y;
            const __half2 r2 = *(const __half2*)&rv.z, r3 = *(const __half2*)&rv.w;
            const __half2 l0 = *(const __half2*)&lv.x, l1 = *(const __half2*)&lv.y;
            const __half2 l2 = *(const __half2*)&lv.z, l3 = *(const __half2*)&lv.w;
            const __half2 h0 = *(const __half2*)&hv.x, h1 = *(const __half2*)&hv.y;
            const __half2 h2 = *(const __half2*)&hv.z, h3 = *(const __half2*)&hv.w;
            sa = __hfma2(r0, h0, sa); sb = __hfma2(r1, h1, sb);
            sa = __hfma2(r2, h2, sa); sb = __hfma2(r3, h3, sb);
            ta = __hfma2(r0, l0, ta); tb = __hfma2(r1, l1, tb);
            ta = __hfma2(r2, l2, ta); tb = __hfma2(r3, l3, tb);
        }
        const float s  = __low2float(sa) + __high2float(sa)
                       + __low2float(sb) + __high2float(sb);
        const float s1 = __low2float(ta) + __high2float(ta)
                       + __low2float(tb) + __high2float(tb);
        ee[tid] = (s + qrow[ro[tid]]) * 0.125f;
        e1[tid] = s1 * 0.125f;
    }
    __syncthreads();

    // two softmaxes over L (warp 0); emit duplicated half2 alphas
    if (wid == 0) {
        float m = -1e30f, m1 = -1e30f;
        for (int l = lane; l < L; l += 32) {
            m  = fmaxf(m,  ee[l]);
            m1 = fmaxf(m1, e1[l]);
        }
#pragma unroll
        for (int o = 16; o > 0; o >>= 1) {
            m  = fmaxf(m,  __shfl_xor_sync(0xffffffffu, m,  o));
            m1 = fmaxf(m1, __shfl_xor_sync(0xffffffffu, m1, o));
        }
        float s = 0.f, s1 = 0.f;
        for (int l = lane; l < L; l += 32) {
            const float a  = __expf(ee[l] - m);
            const float a1 = __expf(e1[l] - m1);
            ee[l] = a;  e1[l] = a1;
            s += a;  s1 += a1;
        }
#pragma unroll
        for (int o = 16; o > 0; o >>= 1) {
            s  += __shfl_xor_sync(0xffffffffu, s,  o);
            s1 += __shfl_xor_sync(0xffffffffu, s1, o);
        }
        const float inv = 1.f / s, inv1 = 1.f / s1;
        for (int l = lane; l < L; l += 32) {
            const float a  = ee[l] * inv;
            const float a1 = e1[l] * inv1;
            ee[l] = a;
            eep[l] = __half2half2(__float2half(a));
            e1p[l] = __half2half2(__float2half(a1));
        }
    }
    __syncthreads();

    // weighted mailbox sums: warp0, half2, 2 cols/thread, dual accumulators
    if (tid < 32) {
        __half2 al0 = __float2half2_rn(0.f), al1 = al0, as0 = al0, as1 = al0;
#pragma unroll
        for (int l = 0; l < L; l += 2) {
            const __half2 m0 = *(const __half2*)&mb[l][2 * tid];
            al0 = __hfma2(eep[l], m0, al0);
            as0 = __hfma2(e1p[l], m0, as0);
            const __half2 m1 = *(const __half2*)&mb[l + 1][2 * tid];
            al1 = __hfma2(eep[l + 1], m1, al1);
            as1 = __hfma2(e1p[l + 1], m1, as1);
        }
        *(__half2*)&mrow[2 * tid]     = __hadd2(al0, al1);
        *(__half2*)&mrow[D + 2 * tid] = __hadd2(as0, as1);
    }
    if (tid < L) mrow[2 * D + ro[tid]] = __float2half(ee[tid]);
    else         mrow[2 * D + tid]     = __half(0.f);   // pad 178..191
}

// ---------------------------------------------------------------------------
// epilogue (HMMA): out = elu(m(fp16) @ Wcat(fp16) + feat).
// A-tile staged in smem (coalesced float4), wmma a-frags from smem, b L1-hot.
// ---------------------------------------------------------------------------
#define ASTR 208   // smem A row stride in halves (416B, 16B-aligned)

__global__ __launch_bounds__(256) void epilogue(
    const float* __restrict__ user_feat, const float* __restrict__ item_feat,
    float* __restrict__ user_out,        float* __restrict__ item_out)
{
    const bool item = blockIdx.x < EIB;
    const int  nb   = item ? blockIdx.x * 64 : NI + (blockIdx.x - EIB) * 64;
    const __half* Wc  = g_wch[item ? 0 : 1];
    const float* feat = item ? item_feat : user_feat;
    float* out        = item ? item_out  : user_out;
    const int base    = item ? nb : nb - NI;
    const int Nloc    = item ? NI : NU;

    __shared__ __align__(16) __half As[64 * ASTR];
    __shared__ float ot[64 * 72];

    const int t = threadIdx.x, w = t >> 5;
    const int rt  = w >> 1;          // row tile 0..3
    const int ct0 = (w & 1) * 2;     // col tiles ct0, ct0+1

    // stage 64x192 A tile (g_m rows nb..nb+63; pad rows are zero-initialized)
    {
        const __half* asrc = g_m + (size_t)nb * KMP;
#pragma unroll
        for (int i = t; i < 64 * (KMP / 8); i += 256) {
            const int row = i / (KMP / 8), c8 = i % (KMP / 8);
            *(float4*)&As[row * ASTR + c8 * 8] =
                *(const float4*)&asrc[row * KMP + c8 * 8];
        }
    }
    __syncthreads();

    wmma::fragment<wmma::accumulator, 16, 16, 16, float> acc0, acc1;
    wmma::fill_fragment(acc0, 0.f);
    wmma::fill_fragment(acc1, 0.f);

#pragma unroll
    for (int kt = 0; kt < KMP / 16; kt++) {
        wmma::fragment<wmma::matrix_a, 16, 16, 16, __half, wmma::row_major> af;
        wmma::load_matrix_sync(af, &As[(rt * 16) * ASTR + kt * 16], ASTR);
        wmma::fragment<wmma::matrix_b, 16, 16, 16, __half, wmma::row_major> bf;
        wmma::load_matrix_sync(bf, Wc + kt * 16 * D + ct0 * 16, D);
        wmma::mma_sync(acc0, af, bf, acc0);
        wmma::load_matrix_sync(bf, Wc + kt * 16 * D + (ct0 + 1) * 16, D);
        wmma::mma_sync(acc1, af, bf, acc1);
    }
    wmma::store_matrix_sync(&ot[(rt * 16) * 72 + ct0 * 16],       acc0, 72, wmma::mem_row_major);
    wmma::store_matrix_sync(&ot[(rt * 16) * 72 + (ct0 + 1) * 16], acc1, 72, wmma::mem_row_major);
    __syncthreads();

    // residual + ELU, vectorized
    const int col = (t & 15) * 4, r0 = t >> 4;
#pragma unroll
    for (int i = 0; i < 4; i++) {
        const int row = r0 + i * 16;
        const int nl  = base + row;
        if (nl < Nloc) {
            const float4 fv = *(const float4*)&feat[nl * D + col];
            const float4 av = *(const float4*)&ot[row * 72 + col];
            float4 r;
            r.x = av.x + fv.x;  r.x = r.x > 0.f ? r.x : expm1f(r.x);
            r.y = av.y + fv.y;  r.y = r.y > 0.f ? r.y : expm1f(r.y);
            r.z = av.z + fv.z;  r.z = r.z > 0.f ? r.z : expm1f(r.z);
            r.w = av.w + fv.w;  r.w = r.w > 0.f ? r.w : expm1f(r.w);
            *(float4*)&out[nl * D + col] = r;
        }
    }
}

// ---------------------------------------------------------------------------
extern "C" void kernel_launch(void* const* d_in, const int* in_sizes, int n_in,
                              void* d_out, int out_size) {
    const float* user_feat = (const float*)d_in[0];
    const float* item_feat = (const float*)d_in[1];
    const float* W_u       = (const float*)d_in[2];
    const float* W_i       = (const float*)d_in[3];
    const float* Wg_u      = (const float*)d_in[4];
    const float* Wg_i      = (const float*)d_in[5];
    const float* i_te      = (const float*)d_in[6];
    const float* i_te_k    = (const float*)d_in[7];
    const float* u_te      = (const float*)d_in[8];
    const float* u_te_k    = (const float*)d_in[9];
    const int*   item_nbr  = (const int*)d_in[10];
    const int*   item_time = (const int*)d_in[11];
    const int*   user_nbr  = (const int*)d_in[12];
    const int*   user_time = (const int*)d_in[13];

    float* user_out = (float*)d_out;            // [NU, D]
    float* item_out = (float*)d_out + NU * D;   // [NI, D]

    prep<<<4, 256>>>(Wg_i, i_te_k, Wg_u, u_te_k, i_te, u_te, W_i, W_u);
    projq<<<PB + QB, 256>>>(user_feat, item_feat, W_u, W_i);
    attn_all<<<NT, 64>>>(item_nbr, item_time, user_nbr, user_time);
    epilogue<<<EIB + EUB, 256>>>(user_feat, item_feat, user_out, item_out);
}